// round 2
// baseline (speedup 1.0000x reference)
#include <cuda_runtime.h>

#define BDIM 2048
#define TDIM 128
#define FDIM 8
#define UO   128
#define UI   64
#define BT   16          // batch rows per CTA
#define NTHR 512
#define HP   18          // padded row stride (floats) for transposed h in smem
#define BN_EPS 1e-3f

// ---------------- device scratch: BN-folded, gate-contiguous weights ---------
// Layout: Wt[(k*U + u)*4 + g]  ->  one float4 load gives all 4 gate weights.
__device__ float g_s1[UO], g_sh1[UO];
__device__ float g_s2[UI], g_sh2[UI];
__device__ float g_s3[UI], g_sh3[UI];
__device__ float g_s4[UO], g_sh4[UO];

__device__ float g_Wk1t[FDIM * UO * 4];
__device__ float g_Wr1t[UO * UO * 4];
__device__ float g_Wr2t[UI * UI * 4];
__device__ float g_Wr3t[UI * UI * 4];
__device__ float g_Wr4t[UO * UO * 4];
__device__ float g_Wk2f[UO * UI * 4];   // BN1 folded
__device__ float g_Wk3f[UI * UI * 4];   // BN2 folded
__device__ float g_Wk4f[UI * UO * 4];   // BN3 folded
__device__ float g_Wdf[UO * FDIM];      // BN4 folded
__device__ float g_b2f[4 * UI];
__device__ float g_b3f[4 * UI];
__device__ float g_b4f[4 * UO];
__device__ float g_bdf[FDIM];

// ---------------- helpers ----------------------------------------------------
__device__ __forceinline__ float2 ffma2f(float2 a, float2 b, float2 c) {
    union U { float2 f; unsigned long long u; };
    U A, B, C, D;
    A.f = a; B.f = b; C.f = c;
    asm("fma.rn.f32x2 %0, %1, %2, %3;" : "=l"(D.u) : "l"(A.u), "l"(B.u), "l"(C.u));
    return D.f;
}

__device__ __forceinline__ float sigm(float x) { return 1.0f / (1.0f + __expf(-x)); }

__device__ __forceinline__ float seluf(float x) {
    const float l = 1.0507009873554805f;
    const float a = 1.6732632423543772f;
    return x > 0.0f ? l * x : l * a * (__expf(x) - 1.0f);
}

__device__ __forceinline__ void gate_update(float zi, float zf, float zg, float zo,
                                            float& c, float& h) {
    float i = sigm(zi), f = sigm(zf), g = seluf(zg), o = sigm(zo);
    c = f * c + i * g;
    h = o * seluf(c);
}

// acc[gate][rowpair] += h_pair * w[gate]; one float4 LDG gets all 4 gate weights
template <int NP>
__device__ __forceinline__ void fma4(float2 (&acc)[4][NP], const float4* __restrict__ wp,
                                     const float* __restrict__ hb) {
    float4 w = __ldg(wp);
    float2 hh[NP];
#pragma unroll
    for (int p = 0; p < NP; p++) hh[p] = *(const float2*)(hb + 2 * p);
    float ws[4] = {w.x, w.y, w.z, w.w};
#pragma unroll
    for (int g = 0; g < 4; g++) {
        float2 W = make_float2(ws[g], ws[g]);
#pragma unroll
        for (int p = 0; p < NP; p++) acc[g][p] = ffma2f(hh[p], W, acc[g][p]);
    }
}

template <int NP>
__device__ __forceinline__ void init_acc(float2 (&acc)[4][NP], const float b[4]) {
#pragma unroll
    for (int g = 0; g < 4; g++)
#pragma unroll
        for (int p = 0; p < NP; p++) acc[g][p] = make_float2(b[g], b[g]);
}

template <int NP>
__device__ __forceinline__ void gates_write(float2 (&acc)[4][NP], float* cvec, float* hrow) {
#pragma unroll
    for (int p = 0; p < NP; p++) {
        {
            float c = cvec[2 * p], h;
            gate_update(acc[0][p].x, acc[1][p].x, acc[2][p].x, acc[3][p].x, c, h);
            cvec[2 * p] = c; hrow[2 * p] = h;
        }
        {
            float c = cvec[2 * p + 1], h;
            gate_update(acc[0][p].y, acc[1][p].y, acc[2][p].y, acc[3][p].y, c, h);
            cvec[2 * p + 1] = c; hrow[2 * p + 1] = h;
        }
    }
}

// ---------------- prep 1: BN scale/shift vectors ------------------------------
__global__ void prep_scales(const float* __restrict__ g1, const float* __restrict__ be1,
                            const float* __restrict__ m1, const float* __restrict__ v1,
                            const float* __restrict__ g2, const float* __restrict__ be2,
                            const float* __restrict__ m2, const float* __restrict__ v2,
                            const float* __restrict__ g3, const float* __restrict__ be3,
                            const float* __restrict__ m3, const float* __restrict__ v3,
                            const float* __restrict__ g4, const float* __restrict__ be4,
                            const float* __restrict__ m4, const float* __restrict__ v4) {
    int i = threadIdx.x;
    if (i < UO) {
        float s = g1[i] * rsqrtf(v1[i] + BN_EPS);
        g_s1[i] = s; g_sh1[i] = be1[i] - m1[i] * s;
        s = g4[i] * rsqrtf(v4[i] + BN_EPS);
        g_s4[i] = s; g_sh4[i] = be4[i] - m4[i] * s;
    }
    if (i < UI) {
        float s = g2[i] * rsqrtf(v2[i] + BN_EPS);
        g_s2[i] = s; g_sh2[i] = be2[i] - m2[i] * s;
        s = g3[i] * rsqrtf(v3[i] + BN_EPS);
        g_s3[i] = s; g_sh3[i] = be3[i] - m3[i] * s;
    }
}

// ---------------- prep 2: transpose to gate-contiguous + fold BN --------------
#define N_WK1T  (FDIM * UO * 4)                       // 4096
#define N_WR1T  (UO * UO * 4)                         // 65536
#define N_WR2T  (UI * UI * 4)                         // 16384
#define N_WR3T  (UI * UI * 4)
#define N_WR4T  (UO * UO * 4)
#define N_WK2F  (UO * UI * 4)                         // 32768
#define N_WK3F  (UI * UI * 4)
#define N_WK4F  (UI * UO * 4)
#define N_WDF   (UO * FDIM)
#define O1 N_WK1T
#define O2 (O1 + N_WR1T)
#define O3 (O2 + N_WR2T)
#define O4 (O3 + N_WR3T)
#define O5 (O4 + N_WR4T)
#define O6 (O5 + N_WK2F)
#define O7 (O6 + N_WK3F)
#define O8 (O7 + N_WK4F)
#define O9 (O8 + N_WDF)
#define OA (O9 + 4 * UI)     // b2f
#define OB (OA + 4 * UI)     // b3f
#define OC (OB + 4 * UO)     // b4f
#define OD (OC + FDIM)       // bdf
#define NTOT OD

__global__ void prep_fold(const float* __restrict__ Wk1, const float* __restrict__ Wr1,
                          const float* __restrict__ Wr2, const float* __restrict__ Wr3,
                          const float* __restrict__ Wr4,
                          const float* __restrict__ Wk2, const float* __restrict__ b2,
                          const float* __restrict__ Wk3, const float* __restrict__ b3,
                          const float* __restrict__ Wk4, const float* __restrict__ b4,
                          const float* __restrict__ Wd,  const float* __restrict__ bd) {
    int e = blockIdx.x * blockDim.x + threadIdx.x;
    if (e >= NTOT) return;
    if (e < O1) {                               // Wk1t: [8][128][4]
        int g = e & 3, u = (e >> 2) & (UO - 1), k = e >> 9;
        g_Wk1t[e] = Wk1[k * 4 * UO + g * UO + u];
    } else if (e < O2) {                        // Wr1t: [128][128][4]
        int i = e - O1;
        int g = i & 3, u = (i >> 2) & (UO - 1), k = i >> 9;
        g_Wr1t[i] = Wr1[k * 4 * UO + g * UO + u];
    } else if (e < O3) {                        // Wr2t: [64][64][4]
        int i = e - O2;
        int g = i & 3, u = (i >> 2) & (UI - 1), k = i >> 8;
        g_Wr2t[i] = Wr2[k * 4 * UI + g * UI + u];
    } else if (e < O4) {                        // Wr3t
        int i = e - O3;
        int g = i & 3, u = (i >> 2) & (UI - 1), k = i >> 8;
        g_Wr3t[i] = Wr3[k * 4 * UI + g * UI + u];
    } else if (e < O5) {                        // Wr4t
        int i = e - O4;
        int g = i & 3, u = (i >> 2) & (UO - 1), k = i >> 9;
        g_Wr4t[i] = Wr4[k * 4 * UO + g * UO + u];
    } else if (e < O6) {                        // Wk2f: [128][64][4], scale s1[k]
        int i = e - O5;
        int g = i & 3, u = (i >> 2) & (UI - 1), k = i >> 8;
        g_Wk2f[i] = g_s1[k] * Wk2[k * 4 * UI + g * UI + u];
    } else if (e < O7) {                        // Wk3f: [64][64][4], scale s2[k]
        int i = e - O6;
        int g = i & 3, u = (i >> 2) & (UI - 1), k = i >> 8;
        g_Wk3f[i] = g_s2[k] * Wk3[k * 4 * UI + g * UI + u];
    } else if (e < O8) {                        // Wk4f: [64][128][4], scale s3[k]
        int i = e - O7;
        int g = i & 3, u = (i >> 2) & (UO - 1), k = i >> 9;
        g_Wk4f[i] = g_s3[k] * Wk4[k * 4 * UO + g * UO + u];
    } else if (e < O9) {                        // Wdf: [128][8], scale s4[k]
        int i = e - O8;
        int k = i >> 3;
        g_Wdf[i] = g_s4[k] * Wd[i];
    } else if (e < OA) {                        // b2f
        int c = e - O9;
        float acc = b2[c];
        for (int k = 0; k < UO; k++) acc += g_sh1[k] * Wk2[k * 4 * UI + c];
        g_b2f[c] = acc;
    } else if (e < OB) {                        // b3f
        int c = e - OA;
        float acc = b3[c];
        for (int k = 0; k < UI; k++) acc += g_sh2[k] * Wk3[k * 4 * UI + c];
        g_b3f[c] = acc;
    } else if (e < OC) {                        // b4f
        int c = e - OB;
        float acc = b4[c];
        for (int k = 0; k < UI; k++) acc += g_sh3[k] * Wk4[k * 4 * UO + c];
        g_b4f[c] = acc;
    } else {                                    // bdf
        int c = e - OC;
        float acc = bd[c];
        for (int k = 0; k < UO; k++) acc += g_sh4[k] * Wd[k * FDIM + c];
        g_bdf[c] = acc;
    }
}

// ---------------- main: full autoencoder, one CTA per 16 batch rows ----------
__global__ __launch_bounds__(NTHR, 1)
void lstm_ae_kernel(const float* __restrict__ x,
                    const float* __restrict__ b1,
                    float* __restrict__ out) {
    __shared__ float h1s[UO * HP];
    __shared__ float h2s[UI * HP];
    __shared__ float h3s[UI * HP];
    __shared__ float h4s[UO * HP];
    __shared__ float xs[FDIM * HP];
    __shared__ float wds[UO * FDIM];
    __shared__ float bds[FDIM];

    const int tid  = threadIdx.x;
    const int row0 = blockIdx.x * BT;

    // big mapping (512-col GEMMs z1/z4): gate-quad u, 4 rows (2 pairs)
    const int ub = tid & 127;
    const int rb = (tid >> 7) * 4;
    // small mapping (256-col GEMMs z2/z3): gate-quad u, 2 rows (1 pair)
    const int us = tid & 63;
    const int rs = (tid >> 6) * 2;

    for (int i = tid; i < UO * HP; i += NTHR) { h1s[i] = 0.f; h4s[i] = 0.f; }
    for (int i = tid; i < UI * HP; i += NTHR) { h2s[i] = 0.f; h3s[i] = 0.f; }
    for (int i = tid; i < UO * FDIM; i += NTHR) wds[i] = g_Wdf[i];
    if (tid < FDIM) bds[tid] = g_bdf[tid];
    if (tid < BT * FDIM) {
        int r = tid >> 3, k = tid & 7;
        xs[k * HP + r] = x[(size_t)(row0 + r) * TDIM * FDIM + k];
    }

    float bb1[4], bb2[4], bb4[4];
#pragma unroll
    for (int g = 0; g < 4; g++) {
        bb1[g] = b1[g * UO + ub];
        bb2[g] = g_b2f[g * UI + us];
        bb4[g] = g_b4f[g * UO + ub];
    }

    float c1v[4], c4v[4], c2v[2], c3v[2];
#pragma unroll
    for (int i = 0; i < 4; i++) { c1v[i] = 0.f; c4v[i] = 0.f; }
#pragma unroll
    for (int i = 0; i < 2; i++) { c2v[i] = 0.f; c3v[i] = 0.f; }

    const float4* Wk1t = (const float4*)g_Wk1t;
    const float4* Wr1t = (const float4*)g_Wr1t;
    const float4* Wr2t = (const float4*)g_Wr2t;
    const float4* Wr3t = (const float4*)g_Wr3t;
    const float4* Wr4t = (const float4*)g_Wr4t;
    const float4* Wk2f = (const float4*)g_Wk2f;
    const float4* Wk3f = (const float4*)g_Wk3f;
    const float4* Wk4f = (const float4*)g_Wk4f;

    __syncthreads();

    // ================= Phase A: encoder (LSTM1 -> BN1 -> LSTM2) ==============
    for (int t = 0; t < TDIM; t++) {
        // z1 = x_t@Wk1 + b1 + h1@Wr1   (reads h1s OLD)
        float2 a1[4][2];
        init_acc<2>(a1, bb1);
#pragma unroll
        for (int k = 0; k < FDIM; k++)
            fma4<2>(a1, Wk1t + k * UO + ub, xs + k * HP + rb);
#pragma unroll 8
        for (int k = 0; k < UO; k++)
            fma4<2>(a1, Wr1t + k * UO + ub, h1s + k * HP + rb);

        // z2 recurrent part = h2@Wr2   (reads h2s OLD)
        float2 a2[4][1];
        init_acc<1>(a2, bb2);
#pragma unroll 8
        for (int k = 0; k < UI; k++)
            fma4<1>(a2, Wr2t + k * UI + us, h2s + k * HP + rs);

        __syncthreads();  // all old-state reads complete

        gates_write<2>(a1, c1v, h1s + ub * HP + rb);   // write h1 NEW
        if (t + 1 < TDIM && tid < BT * FDIM) {         // prefetch x_{t+1}
            int r = tid >> 3, k = tid & 7;
            xs[k * HP + r] = x[(size_t)(row0 + r) * TDIM * FDIM + (t + 1) * FDIM + k];
        }
        __syncthreads();  // h1 NEW visible

        // z2 input part = h1_new @ Wk2f (BN1 folded)
#pragma unroll 8
        for (int k = 0; k < UO; k++)
            fma4<1>(a2, Wk2f + k * UI + us, h1s + k * HP + rs);

        gates_write<1>(a2, c2v, h2s + us * HP + rs);   // write h2 NEW
        __syncthreads();
    }

    // ============ transition: xz3 = enc_bn @ Wk3f + b3f (constant over t) ====
    float2 x3[4][1];
    {
        float bb3[4];
#pragma unroll
        for (int g = 0; g < 4; g++) bb3[g] = g_b3f[g * UI + us];
        init_acc<1>(x3, bb3);
#pragma unroll 8
        for (int k = 0; k < UI; k++)
            fma4<1>(x3, Wk3f + k * UI + us, h2s + k * HP + rs);
    }

    // ============ Phase B: decoder (LSTM3 -> BN3 -> LSTM4 -> BN4 -> Dense) ===
    const int dr = tid >> 3, dc = tid & 7;  // dense mapping (tid < 128)
    for (int t = 0; t < TDIM; t++) {
        // z3 = xz3 + h3@Wr3  (reads h3s OLD)
        float2 a3[4][1];
#pragma unroll
        for (int g = 0; g < 4; g++) a3[g][0] = x3[g][0];
#pragma unroll 8
        for (int k = 0; k < UI; k++)
            fma4<1>(a3, Wr3t + k * UI + us, h3s + k * HP + rs);

        // z4 recurrent part = h4@Wr4  (reads h4s OLD)
        float2 a4[4][2];
        init_acc<2>(a4, bb4);
#pragma unroll 8
        for (int k = 0; k < UO; k++)
            fma4<2>(a4, Wr4t + k * UO + ub, h4s + k * HP + rb);

        __syncthreads();  // all old-state reads complete

        gates_write<1>(a3, c3v, h3s + us * HP + rs);   // write h3 NEW
        __syncthreads();  // h3 NEW visible

        // z4 input part = h3_new @ Wk4f (BN3 folded)
#pragma unroll 8
        for (int k = 0; k < UI; k++)
            fma4<2>(a4, Wk4f + k * UO + ub, h3s + k * HP + rb);

        gates_write<2>(a4, c4v, h4s + ub * HP + rb);   // write h4 NEW
        __syncthreads();  // h4 NEW visible

        // dense head (BN4 folded): out[:, t, :] = h4_new @ Wdf + bdf
        if (tid < BT * FDIM) {
            float acc = bds[dc];
#pragma unroll 8
            for (int k = 0; k < UO; k++) acc += h4s[k * HP + dr] * wds[k * FDIM + dc];
            out[(size_t)(row0 + dr) * TDIM * FDIM + t * FDIM + dc] = acc;
        }
    }
}

// ---------------- launch ------------------------------------------------------
extern "C" void kernel_launch(void* const* d_in, const int* in_sizes, int n_in,
                              void* d_out, int out_size) {
    const float* x   = (const float*)d_in[0];
    const float* Wk1 = (const float*)d_in[1];
    const float* Wr1 = (const float*)d_in[2];
    const float* b1  = (const float*)d_in[3];
    const float* g1  = (const float*)d_in[4];
    const float* be1 = (const float*)d_in[5];
    const float* m1  = (const float*)d_in[6];
    const float* v1  = (const float*)d_in[7];
    const float* Wk2 = (const float*)d_in[8];
    const float* Wr2 = (const float*)d_in[9];
    const float* b2  = (const float*)d_in[10];
    const float* g2  = (const float*)d_in[11];
    const float* be2 = (const float*)d_in[12];
    const float* m2  = (const float*)d_in[13];
    const float* v2  = (const float*)d_in[14];
    const float* Wk3 = (const float*)d_in[15];
    const float* Wr3 = (const float*)d_in[16];
    const float* b3  = (const float*)d_in[17];
    const float* g3  = (const float*)d_in[18];
    const float* be3 = (const float*)d_in[19];
    const float* m3  = (const float*)d_in[20];
    const float* v3  = (const float*)d_in[21];
    const float* Wk4 = (const float*)d_in[22];
    const float* Wr4 = (const float*)d_in[23];
    const float* b4  = (const float*)d_in[24];
    const float* g4  = (const float*)d_in[25];
    const float* be4 = (const float*)d_in[26];
    const float* m4  = (const float*)d_in[27];
    const float* v4  = (const float*)d_in[28];
    const float* Wd  = (const float*)d_in[29];
    const float* bd  = (const float*)d_in[30];

    prep_scales<<<1, 256>>>(g1, be1, m1, v1, g2, be2, m2, v2,
                            g3, be3, m3, v3, g4, be4, m4, v4);
    prep_fold<<<(NTOT + 255) / 256, 256>>>(Wk1, Wr1, Wr2, Wr3, Wr4,
                                           Wk2, b2, Wk3, b3, Wk4, b4, Wd, bd);
    lstm_ae_kernel<<<BDIM / BT, NTHR>>>(x, b1, (float*)d_out);
}

// round 3
// speedup vs baseline: 1.5589x; 1.5589x over previous
#include <cuda_runtime.h>

#define BDIM 2048
#define TDIM 128
#define FDIM 8
#define UO   128
#define UI   64
#define BT   16          // batch rows per CTA
#define NTHR 256
#define HP   20          // padded row stride (floats), multiple of 4 for LDS.128
#define BN_EPS 1e-3f

// ---------------- device scratch: BN-folded, gate-contiguous weights ---------
// Layout: Wt[(k*U + u)*4 + g]  ->  one float4 load gives all 4 gate weights.
__device__ float g_s1[UO], g_sh1[UO];
__device__ float g_s2[UI], g_sh2[UI];
__device__ float g_s3[UI], g_sh3[UI];
__device__ float g_s4[UO], g_sh4[UO];

__device__ __align__(16) float g_Wk1t[FDIM * UO * 4];
__device__ __align__(16) float g_Wr1t[UO * UO * 4];
__device__ __align__(16) float g_Wr2t[UI * UI * 4];
__device__ __align__(16) float g_Wr3t[UI * UI * 4];
__device__ __align__(16) float g_Wr4t[UO * UO * 4];
__device__ __align__(16) float g_Wk2f[UO * UI * 4];   // BN1 folded
__device__ __align__(16) float g_Wk3f[UI * UI * 4];   // BN2 folded
__device__ __align__(16) float g_Wk4f[UI * UO * 4];   // BN3 folded
__device__ float g_Wdf[UO * FDIM];                    // BN4 folded
__device__ float g_b2f[4 * UI];
__device__ float g_b3f[4 * UI];
__device__ float g_b4f[4 * UO];
__device__ float g_bdf[FDIM];

// ---------------- helpers ----------------------------------------------------
__device__ __forceinline__ float2 ffma2f(float2 a, float2 b, float2 c) {
    union U { float2 f; unsigned long long u; };
    U A, B, C, D;
    A.f = a; B.f = b; C.f = c;
    asm("fma.rn.f32x2 %0, %1, %2, %3;" : "=l"(D.u) : "l"(A.u), "l"(B.u), "l"(C.u));
    return D.f;
}

__device__ __forceinline__ float sigm(float x) { return 1.0f / (1.0f + __expf(-x)); }

__device__ __forceinline__ float seluf(float x) {
    const float l = 1.0507009873554805f;
    const float a = 1.6732632423543772f;
    return x > 0.0f ? l * x : l * a * (__expf(x) - 1.0f);
}

__device__ __forceinline__ void gate_update(float zi, float zf, float zg, float zo,
                                            float& c, float& h) {
    float i = sigm(zi), f = sigm(zf), g = seluf(zg), o = sigm(zo);
    c = f * c + i * g;
    h = o * seluf(c);
}

// NQ float4 row-quads (4 rows each): acc[g][2q],acc[g][2q+1] cover rows 4q..4q+3
template <int NQ>
__device__ __forceinline__ void fma4q(float2 (&acc)[4][2 * NQ],
                                      const float4* __restrict__ wp,
                                      const float4* __restrict__ hb) {
    float4 w = __ldg(wp);
    float4 h[NQ];
#pragma unroll
    for (int q = 0; q < NQ; q++) h[q] = hb[q];
    float ws[4] = {w.x, w.y, w.z, w.w};
#pragma unroll
    for (int g = 0; g < 4; g++) {
        float2 W = make_float2(ws[g], ws[g]);
#pragma unroll
        for (int q = 0; q < NQ; q++) {
            acc[g][2 * q]     = ffma2f(make_float2(h[q].x, h[q].y), W, acc[g][2 * q]);
            acc[g][2 * q + 1] = ffma2f(make_float2(h[q].z, h[q].w), W, acc[g][2 * q + 1]);
        }
    }
}

template <int NP>
__device__ __forceinline__ void init_acc(float2 (&acc)[4][NP], const float b[4]) {
#pragma unroll
    for (int g = 0; g < 4; g++)
#pragma unroll
        for (int p = 0; p < NP; p++) acc[g][p] = make_float2(b[g], b[g]);
}

template <int NP>
__device__ __forceinline__ void gates_write(float2 (&acc)[4][NP], float* cvec, float* hrow) {
#pragma unroll
    for (int p = 0; p < NP; p++) {
        {
            float c = cvec[2 * p], h;
            gate_update(acc[0][p].x, acc[1][p].x, acc[2][p].x, acc[3][p].x, c, h);
            cvec[2 * p] = c; hrow[2 * p] = h;
        }
        {
            float c = cvec[2 * p + 1], h;
            gate_update(acc[0][p].y, acc[1][p].y, acc[2][p].y, acc[3][p].y, c, h);
            cvec[2 * p + 1] = c; hrow[2 * p + 1] = h;
        }
    }
}

// ---------------- prep 1: BN scale/shift vectors ------------------------------
__global__ void prep_scales(const float* __restrict__ g1, const float* __restrict__ be1,
                            const float* __restrict__ m1, const float* __restrict__ v1,
                            const float* __restrict__ g2, const float* __restrict__ be2,
                            const float* __restrict__ m2, const float* __restrict__ v2,
                            const float* __restrict__ g3, const float* __restrict__ be3,
                            const float* __restrict__ m3, const float* __restrict__ v3,
                            const float* __restrict__ g4, const float* __restrict__ be4,
                            const float* __restrict__ m4, const float* __restrict__ v4) {
    int i = threadIdx.x;
    if (i < UO) {
        float s = g1[i] * rsqrtf(v1[i] + BN_EPS);
        g_s1[i] = s; g_sh1[i] = be1[i] - m1[i] * s;
        s = g4[i] * rsqrtf(v4[i] + BN_EPS);
        g_s4[i] = s; g_sh4[i] = be4[i] - m4[i] * s;
    }
    if (i < UI) {
        float s = g2[i] * rsqrtf(v2[i] + BN_EPS);
        g_s2[i] = s; g_sh2[i] = be2[i] - m2[i] * s;
        s = g3[i] * rsqrtf(v3[i] + BN_EPS);
        g_s3[i] = s; g_sh3[i] = be3[i] - m3[i] * s;
    }
}

// ---------------- prep 2: transpose to gate-contiguous + fold BN --------------
#define N_WK1T  (FDIM * UO * 4)
#define N_WR1T  (UO * UO * 4)
#define N_WR2T  (UI * UI * 4)
#define N_WR3T  (UI * UI * 4)
#define N_WR4T  (UO * UO * 4)
#define N_WK2F  (UO * UI * 4)
#define N_WK3F  (UI * UI * 4)
#define N_WK4F  (UI * UO * 4)
#define N_WDF   (UO * FDIM)
#define O1 N_WK1T
#define O2 (O1 + N_WR1T)
#define O3 (O2 + N_WR2T)
#define O4 (O3 + N_WR3T)
#define O5 (O4 + N_WR4T)
#define O6 (O5 + N_WK2F)
#define O7 (O6 + N_WK3F)
#define O8 (O7 + N_WK4F)
#define O9 (O8 + N_WDF)
#define OA (O9 + 4 * UI)
#define OB (OA + 4 * UI)
#define OC (OB + 4 * UO)
#define OD (OC + FDIM)
#define NTOT OD

__global__ void prep_fold(const float* __restrict__ Wk1, const float* __restrict__ Wr1,
                          const float* __restrict__ Wr2, const float* __restrict__ Wr3,
                          const float* __restrict__ Wr4,
                          const float* __restrict__ Wk2, const float* __restrict__ b2,
                          const float* __restrict__ Wk3, const float* __restrict__ b3,
                          const float* __restrict__ Wk4, const float* __restrict__ b4,
                          const float* __restrict__ Wd,  const float* __restrict__ bd) {
    int e = blockIdx.x * blockDim.x + threadIdx.x;
    if (e >= NTOT) return;
    if (e < O1) {
        int g = e & 3, u = (e >> 2) & (UO - 1), k = e >> 9;
        g_Wk1t[e] = Wk1[k * 4 * UO + g * UO + u];
    } else if (e < O2) {
        int i = e - O1;
        int g = i & 3, u = (i >> 2) & (UO - 1), k = i >> 9;
        g_Wr1t[i] = Wr1[k * 4 * UO + g * UO + u];
    } else if (e < O3) {
        int i = e - O2;
        int g = i & 3, u = (i >> 2) & (UI - 1), k = i >> 8;
        g_Wr2t[i] = Wr2[k * 4 * UI + g * UI + u];
    } else if (e < O4) {
        int i = e - O3;
        int g = i & 3, u = (i >> 2) & (UI - 1), k = i >> 8;
        g_Wr3t[i] = Wr3[k * 4 * UI + g * UI + u];
    } else if (e < O5) {
        int i = e - O4;
        int g = i & 3, u = (i >> 2) & (UO - 1), k = i >> 9;
        g_Wr4t[i] = Wr4[k * 4 * UO + g * UO + u];
    } else if (e < O6) {
        int i = e - O5;
        int g = i & 3, u = (i >> 2) & (UI - 1), k = i >> 8;
        g_Wk2f[i] = g_s1[k] * Wk2[k * 4 * UI + g * UI + u];
    } else if (e < O7) {
        int i = e - O6;
        int g = i & 3, u = (i >> 2) & (UI - 1), k = i >> 8;
        g_Wk3f[i] = g_s2[k] * Wk3[k * 4 * UI + g * UI + u];
    } else if (e < O8) {
        int i = e - O7;
        int g = i & 3, u = (i >> 2) & (UO - 1), k = i >> 9;
        g_Wk4f[i] = g_s3[k] * Wk4[k * 4 * UO + g * UO + u];
    } else if (e < O9) {
        int i = e - O8;
        int k = i >> 3;
        g_Wdf[i] = g_s4[k] * Wd[i];
    } else if (e < OA) {
        int c = e - O9;
        float acc = b2[c];
        for (int k = 0; k < UO; k++) acc += g_sh1[k] * Wk2[k * 4 * UI + c];
        g_b2f[c] = acc;
    } else if (e < OB) {
        int c = e - OA;
        float acc = b3[c];
        for (int k = 0; k < UI; k++) acc += g_sh2[k] * Wk3[k * 4 * UI + c];
        g_b3f[c] = acc;
    } else if (e < OC) {
        int c = e - OB;
        float acc = b4[c];
        for (int k = 0; k < UI; k++) acc += g_sh3[k] * Wk4[k * 4 * UO + c];
        g_b4f[c] = acc;
    } else {
        int c = e - OC;
        float acc = bd[c];
        for (int k = 0; k < UO; k++) acc += g_sh4[k] * Wd[k * FDIM + c];
        g_bdf[c] = acc;
    }
}

// ---------------- main: full autoencoder, one CTA per 16 batch rows ----------
__global__ __launch_bounds__(NTHR, 1)
void lstm_ae_kernel(const float* __restrict__ x,
                    const float* __restrict__ b1,
                    float* __restrict__ out) {
    __shared__ __align__(16) float h1s[UO * HP];
    __shared__ __align__(16) float h2s[UI * HP];
    __shared__ __align__(16) float h3s[UI * HP];
    __shared__ __align__(16) float h4s[UO * HP];
    __shared__ __align__(16) float xs[FDIM * HP];
    __shared__ float wds[UO * FDIM];
    __shared__ float bds[FDIM];

    const int tid  = threadIdx.x;
    const int row0 = blockIdx.x * BT;

    // big mapping (512-col GEMMs z1/z4): gate-quad u, 8 rows (2 float4 quads)
    const int ub = tid & 127;
    const int rb = (tid >> 7) * 8;
    // small mapping (256-col GEMMs z2/z3): gate-quad u, 4 rows (1 float4 quad)
    const int us = tid & 63;
    const int rs = (tid >> 6) * 4;

    for (int i = tid; i < UO * HP; i += NTHR) { h1s[i] = 0.f; h4s[i] = 0.f; }
    for (int i = tid; i < UI * HP; i += NTHR) { h2s[i] = 0.f; h3s[i] = 0.f; }
    for (int i = tid; i < UO * FDIM; i += NTHR) wds[i] = g_Wdf[i];
    if (tid < FDIM) bds[tid] = g_bdf[tid];
    if (tid < BT * FDIM) {
        int r = tid >> 3, k = tid & 7;
        xs[k * HP + r] = x[(size_t)(row0 + r) * TDIM * FDIM + k];
    }

    float bb1[4], bb2[4], bb4[4];
#pragma unroll
    for (int g = 0; g < 4; g++) {
        bb1[g] = b1[g * UO + ub];
        bb2[g] = g_b2f[g * UI + us];
        bb4[g] = g_b4f[g * UO + ub];
    }

    float c1v[8], c4v[8], c2v[4], c3v[4];
#pragma unroll
    for (int i = 0; i < 8; i++) { c1v[i] = 0.f; c4v[i] = 0.f; }
#pragma unroll
    for (int i = 0; i < 4; i++) { c2v[i] = 0.f; c3v[i] = 0.f; }

    const float4* Wk1t = (const float4*)g_Wk1t;
    const float4* Wr1t = (const float4*)g_Wr1t;
    const float4* Wr2t = (const float4*)g_Wr2t;
    const float4* Wr3t = (const float4*)g_Wr3t;
    const float4* Wr4t = (const float4*)g_Wr4t;
    const float4* Wk2f = (const float4*)g_Wk2f;
    const float4* Wk3f = (const float4*)g_Wk3f;
    const float4* Wk4f = (const float4*)g_Wk4f;

    __syncthreads();

    // ================= Phase A: encoder (LSTM1 -> BN1 -> LSTM2) ==============
    for (int t = 0; t < TDIM; t++) {
        // z1 = x_t@Wk1 + b1 + h1@Wr1   (reads h1s OLD)
        float2 a1[4][4];
        init_acc<4>(a1, bb1);
#pragma unroll
        for (int k = 0; k < FDIM; k++)
            fma4q<2>(a1, Wk1t + k * UO + ub, (const float4*)(xs + k * HP + rb));
#pragma unroll 8
        for (int k = 0; k < UO; k++)
            fma4q<2>(a1, Wr1t + k * UO + ub, (const float4*)(h1s + k * HP + rb));

        // z2 recurrent part = h2@Wr2   (reads h2s OLD)
        float2 a2[4][2];
        init_acc<2>(a2, bb2);
#pragma unroll 8
        for (int k = 0; k < UI; k++)
            fma4q<1>(a2, Wr2t + k * UI + us, (const float4*)(h2s + k * HP + rs));

        __syncthreads();  // all old-state reads complete

        gates_write<4>(a1, c1v, h1s + ub * HP + rb);   // write h1 NEW
        if (t + 1 < TDIM && tid < BT * FDIM) {         // prefetch x_{t+1}
            int r = tid >> 3, k = tid & 7;
            xs[k * HP + r] = x[(size_t)(row0 + r) * TDIM * FDIM + (t + 1) * FDIM + k];
        }
        __syncthreads();  // h1 NEW visible

        // z2 input part = h1_new @ Wk2f (BN1 folded)
#pragma unroll 8
        for (int k = 0; k < UO; k++)
            fma4q<1>(a2, Wk2f + k * UI + us, (const float4*)(h1s + k * HP + rs));

        gates_write<2>(a2, c2v, h2s + us * HP + rs);   // write h2 NEW
        __syncthreads();
    }

    // ============ transition: xz3 = enc_bn @ Wk3f + b3f (constant over t) ====
    float2 x3[4][2];
    {
        float bb3[4];
#pragma unroll
        for (int g = 0; g < 4; g++) bb3[g] = g_b3f[g * UI + us];
        init_acc<2>(x3, bb3);
#pragma unroll 8
        for (int k = 0; k < UI; k++)
            fma4q<1>(x3, Wk3f + k * UI + us, (const float4*)(h2s + k * HP + rs));
    }

    // ============ Phase B: decoder (LSTM3 -> BN3 -> LSTM4 -> BN4 -> Dense) ===
    const int dr = tid >> 3, dc = tid & 7;  // dense mapping (tid < 128)
    for (int t = 0; t < TDIM; t++) {
        // z3 = xz3 + h3@Wr3  (reads h3s OLD)
        float2 a3[4][2];
#pragma unroll
        for (int g = 0; g < 4; g++) {
            a3[g][0] = x3[g][0]; a3[g][1] = x3[g][1];
        }
#pragma unroll 8
        for (int k = 0; k < UI; k++)
            fma4q<1>(a3, Wr3t + k * UI + us, (const float4*)(h3s + k * HP + rs));

        // z4 recurrent part = h4@Wr4  (reads h4s OLD)
        float2 a4[4][4];
        init_acc<4>(a4, bb4);
#pragma unroll 8
        for (int k = 0; k < UO; k++)
            fma4q<2>(a4, Wr4t + k * UO + ub, (const float4*)(h4s + k * HP + rb));

        // dense head for step t-1 (reads h4s OLD = h4(t-1)), overlapped
        if (t > 0 && tid < BT * FDIM) {
            float acc = bds[dc];
#pragma unroll 8
            for (int k = 0; k < UO; k++) acc += h4s[k * HP + dr] * wds[k * FDIM + dc];
            out[(size_t)(row0 + dr) * TDIM * FDIM + (t - 1) * FDIM + dc] = acc;
        }

        __syncthreads();  // all old-state reads complete

        gates_write<2>(a3, c3v, h3s + us * HP + rs);   // write h3 NEW
        __syncthreads();  // h3 NEW visible

        // z4 input part = h3_new @ Wk4f (BN3 folded)
#pragma unroll 8
        for (int k = 0; k < UI; k++)
            fma4q<2>(a4, Wk4f + k * UO + ub, (const float4*)(h3s + k * HP + rb));

        gates_write<4>(a4, c4v, h4s + ub * HP + rb);   // write h4 NEW
        __syncthreads();  // h4 NEW visible
    }

    // final dense head (t = T-1)
    if (tid < BT * FDIM) {
        float acc = bds[dc];
#pragma unroll 8
        for (int k = 0; k < UO; k++) acc += h4s[k * HP + dr] * wds[k * FDIM + dc];
        out[(size_t)(row0 + dr) * TDIM * FDIM + (TDIM - 1) * FDIM + dc] = acc;
    }
}

// ---------------- launch ------------------------------------------------------
extern "C" void kernel_launch(void* const* d_in, const int* in_sizes, int n_in,
                              void* d_out, int out_size) {
    const float* x   = (const float*)d_in[0];
    const float* Wk1 = (const float*)d_in[1];
    const float* Wr1 = (const float*)d_in[2];
    const float* b1  = (const float*)d_in[3];
    const float* g1  = (const float*)d_in[4];
    const float* be1 = (const float*)d_in[5];
    const float* m1  = (const float*)d_in[6];
    const float* v1  = (const float*)d_in[7];
    const float* Wk2 = (const float*)d_in[8];
    const float* Wr2 = (const float*)d_in[9];
    const float* b2  = (const float*)d_in[10];
    const float* g2  = (const float*)d_in[11];
    const float* be2 = (const float*)d_in[12];
    const float* m2  = (const float*)d_in[13];
    const float* v2  = (const float*)d_in[14];
    const float* Wk3 = (const float*)d_in[15];
    const float* Wr3 = (const float*)d_in[16];
    const float* b3  = (const float*)d_in[17];
    const float* g3  = (const float*)d_in[18];
    const float* be3 = (const float*)d_in[19];
    const float* m3  = (const float*)d_in[20];
    const float* v3  = (const float*)d_in[21];
    const float* Wk4 = (const float*)d_in[22];
    const float* Wr4 = (const float*)d_in[23];
    const float* b4  = (const float*)d_in[24];
    const float* g4  = (const float*)d_in[25];
    const float* be4 = (const float*)d_in[26];
    const float* m4  = (const float*)d_in[27];
    const float* v4  = (const float*)d_in[28];
    const float* Wd  = (const float*)d_in[29];
    const float* bd  = (const float*)d_in[30];

    prep_scales<<<1, 256>>>(g1, be1, m1, v1, g2, be2, m2, v2,
                            g3, be3, m3, v3, g4, be4, m4, v4);
    prep_fold<<<(NTOT + 255) / 256, 256>>>(Wk1, Wr1, Wr2, Wr3, Wr4,
                                           Wk2, b2, Wk3, b3, Wk4, b4, Wd, bd);
    lstm_ae_kernel<<<BDIM / BT, NTHR>>>(x, b1, (float*)d_out);
}

// round 4
// speedup vs baseline: 1.5751x; 1.0104x over previous
#include <cuda_runtime.h>

#define BDIM 2048
#define TDIM 128
#define FDIM 8
#define UO   128
#define UI   64
#define BT   16          // batch rows per CTA (two independent halves of 8)
#define HR   8           // rows per half
#define NTHR 256
#define BN_EPS 1e-3f

// ---------------- device scratch: BN-folded, gate-contiguous weights ---------
// Layout: Wt[(k*U + u)*4 + g]  ->  one float4 load gives all 4 gate weights.
__device__ float g_s1[UO], g_sh1[UO];
__device__ float g_s2[UI], g_sh2[UI];
__device__ float g_s3[UI], g_sh3[UI];
__device__ float g_s4[UO], g_sh4[UO];

__device__ __align__(16) float g_Wk1t[FDIM * UO * 4];
__device__ __align__(16) float g_Wr1t[UO * UO * 4];
__device__ __align__(16) float g_Wr2t[UI * UI * 4];
__device__ __align__(16) float g_Wr3t[UI * UI * 4];
__device__ __align__(16) float g_Wr4t[UO * UO * 4];
__device__ __align__(16) float g_Wk2f[UO * UI * 4];   // BN1 folded
__device__ __align__(16) float g_Wk3f[UI * UI * 4];   // BN2 folded
__device__ __align__(16) float g_Wk4f[UI * UO * 4];   // BN3 folded
__device__ float g_Wdf[UO * FDIM];                    // BN4 folded
__device__ float g_b2f[4 * UI];
__device__ float g_b3f[4 * UI];
__device__ float g_b4f[4 * UO];
__device__ float g_bdf[FDIM];

// ---------------- helpers ----------------------------------------------------
__device__ __forceinline__ float2 ffma2f(float2 a, float2 b, float2 c) {
    union U { float2 f; unsigned long long u; };
    U A, B, C, D;
    A.f = a; B.f = b; C.f = c;
    asm("fma.rn.f32x2 %0, %1, %2, %3;" : "=l"(D.u) : "l"(A.u), "l"(B.u), "l"(C.u));
    return D.f;
}

__device__ __forceinline__ void barsync(int id) {
    asm volatile("bar.sync %0, 128;" :: "r"(id) : "memory");
}

__device__ __forceinline__ float sigm(float x) { return 1.0f / (1.0f + __expf(-x)); }

__device__ __forceinline__ float seluf(float x) {
    const float l = 1.0507009873554805f;
    const float a = 1.6732632423543772f;
    return x > 0.0f ? l * x : l * a * (__expf(x) - 1.0f);
}

__device__ __forceinline__ void gate_update(float zi, float zf, float zg, float zo,
                                            float& c, float& h) {
    float i = sigm(zi), f = sigm(zf), g = seluf(zg), o = sigm(zo);
    c = f * c + i * g;
    h = o * seluf(c);
}

// NQ float4 row-quads (4 rows each): acc[g][2q],acc[g][2q+1] cover rows 4q..4q+3
template <int NQ>
__device__ __forceinline__ void fma4q(float2 (&acc)[4][2 * NQ],
                                      const float4* __restrict__ wp,
                                      const float4* __restrict__ hb) {
    float4 w = __ldg(wp);
    float4 h[NQ];
#pragma unroll
    for (int q = 0; q < NQ; q++) h[q] = hb[q];
    float ws[4] = {w.x, w.y, w.z, w.w};
#pragma unroll
    for (int g = 0; g < 4; g++) {
        float2 W = make_float2(ws[g], ws[g]);
#pragma unroll
        for (int q = 0; q < NQ; q++) {
            acc[g][2 * q]     = ffma2f(make_float2(h[q].x, h[q].y), W, acc[g][2 * q]);
            acc[g][2 * q + 1] = ffma2f(make_float2(h[q].z, h[q].w), W, acc[g][2 * q + 1]);
        }
    }
}

template <int NP>
__device__ __forceinline__ void init_acc(float2 (&acc)[4][NP], const float b[4]) {
#pragma unroll
    for (int g = 0; g < 4; g++)
#pragma unroll
        for (int p = 0; p < NP; p++) acc[g][p] = make_float2(b[g], b[g]);
}

template <int NP>
__device__ __forceinline__ void gates_write(float2 (&acc)[4][NP], float* cvec, float* hrow) {
#pragma unroll
    for (int p = 0; p < NP; p++) {
        {
            float c = cvec[2 * p], h;
            gate_update(acc[0][p].x, acc[1][p].x, acc[2][p].x, acc[3][p].x, c, h);
            cvec[2 * p] = c; hrow[2 * p] = h;
        }
        {
            float c = cvec[2 * p + 1], h;
            gate_update(acc[0][p].y, acc[1][p].y, acc[2][p].y, acc[3][p].y, c, h);
            cvec[2 * p + 1] = c; hrow[2 * p + 1] = h;
        }
    }
}

// ---------------- prep 1: BN scale/shift vectors ------------------------------
__global__ void prep_scales(const float* __restrict__ g1, const float* __restrict__ be1,
                            const float* __restrict__ m1, const float* __restrict__ v1,
                            const float* __restrict__ g2, const float* __restrict__ be2,
                            const float* __restrict__ m2, const float* __restrict__ v2,
                            const float* __restrict__ g3, const float* __restrict__ be3,
                            const float* __restrict__ m3, const float* __restrict__ v3,
                            const float* __restrict__ g4, const float* __restrict__ be4,
                            const float* __restrict__ m4, const float* __restrict__ v4) {
    int i = threadIdx.x;
    if (i < UO) {
        float s = g1[i] * rsqrtf(v1[i] + BN_EPS);
        g_s1[i] = s; g_sh1[i] = be1[i] - m1[i] * s;
        s = g4[i] * rsqrtf(v4[i] + BN_EPS);
        g_s4[i] = s; g_sh4[i] = be4[i] - m4[i] * s;
    }
    if (i < UI) {
        float s = g2[i] * rsqrtf(v2[i] + BN_EPS);
        g_s2[i] = s; g_sh2[i] = be2[i] - m2[i] * s;
        s = g3[i] * rsqrtf(v3[i] + BN_EPS);
        g_s3[i] = s; g_sh3[i] = be3[i] - m3[i] * s;
    }
}

// ---------------- prep 2: transpose to gate-contiguous + fold BN --------------
#define N_WK1T  (FDIM * UO * 4)
#define N_WR1T  (UO * UO * 4)
#define N_WR2T  (UI * UI * 4)
#define N_WR3T  (UI * UI * 4)
#define N_WR4T  (UO * UO * 4)
#define N_WK2F  (UO * UI * 4)
#define N_WK3F  (UI * UI * 4)
#define N_WK4F  (UI * UO * 4)
#define N_WDF   (UO * FDIM)
#define O1 N_WK1T
#define O2 (O1 + N_WR1T)
#define O3 (O2 + N_WR2T)
#define O4 (O3 + N_WR3T)
#define O5 (O4 + N_WR4T)
#define O6 (O5 + N_WK2F)
#define O7 (O6 + N_WK3F)
#define O8 (O7 + N_WK4F)
#define O9 (O8 + N_WDF)
#define OA (O9 + 4 * UI)
#define OB (OA + 4 * UI)
#define OC (OB + 4 * UO)
#define OD (OC + FDIM)
#define NTOT OD

__global__ void prep_fold(const float* __restrict__ Wk1, const float* __restrict__ Wr1,
                          const float* __restrict__ Wr2, const float* __restrict__ Wr3,
                          const float* __restrict__ Wr4,
                          const float* __restrict__ Wk2, const float* __restrict__ b2,
                          const float* __restrict__ Wk3, const float* __restrict__ b3,
                          const float* __restrict__ Wk4, const float* __restrict__ b4,
                          const float* __restrict__ Wd,  const float* __restrict__ bd) {
    int e = blockIdx.x * blockDim.x + threadIdx.x;
    if (e >= NTOT) return;
    if (e < O1) {
        int g = e & 3, u = (e >> 2) & (UO - 1), k = e >> 9;
        g_Wk1t[e] = Wk1[k * 4 * UO + g * UO + u];
    } else if (e < O2) {
        int i = e - O1;
        int g = i & 3, u = (i >> 2) & (UO - 1), k = i >> 9;
        g_Wr1t[i] = Wr1[k * 4 * UO + g * UO + u];
    } else if (e < O3) {
        int i = e - O2;
        int g = i & 3, u = (i >> 2) & (UI - 1), k = i >> 8;
        g_Wr2t[i] = Wr2[k * 4 * UI + g * UI + u];
    } else if (e < O4) {
        int i = e - O3;
        int g = i & 3, u = (i >> 2) & (UI - 1), k = i >> 8;
        g_Wr3t[i] = Wr3[k * 4 * UI + g * UI + u];
    } else if (e < O5) {
        int i = e - O4;
        int g = i & 3, u = (i >> 2) & (UO - 1), k = i >> 9;
        g_Wr4t[i] = Wr4[k * 4 * UO + g * UO + u];
    } else if (e < O6) {
        int i = e - O5;
        int g = i & 3, u = (i >> 2) & (UI - 1), k = i >> 8;
        g_Wk2f[i] = g_s1[k] * Wk2[k * 4 * UI + g * UI + u];
    } else if (e < O7) {
        int i = e - O6;
        int g = i & 3, u = (i >> 2) & (UI - 1), k = i >> 8;
        g_Wk3f[i] = g_s2[k] * Wk3[k * 4 * UI + g * UI + u];
    } else if (e < O8) {
        int i = e - O7;
        int g = i & 3, u = (i >> 2) & (UO - 1), k = i >> 9;
        g_Wk4f[i] = g_s3[k] * Wk4[k * 4 * UO + g * UO + u];
    } else if (e < O9) {
        int i = e - O8;
        int k = i >> 3;
        g_Wdf[i] = g_s4[k] * Wd[i];
    } else if (e < OA) {
        int c = e - O9;
        float acc = b2[c];
        for (int k = 0; k < UO; k++) acc += g_sh1[k] * Wk2[k * 4 * UI + c];
        g_b2f[c] = acc;
    } else if (e < OB) {
        int c = e - OA;
        float acc = b3[c];
        for (int k = 0; k < UI; k++) acc += g_sh2[k] * Wk3[k * 4 * UI + c];
        g_b3f[c] = acc;
    } else if (e < OC) {
        int c = e - OB;
        float acc = b4[c];
        for (int k = 0; k < UI; k++) acc += g_sh3[k] * Wk4[k * 4 * UO + c];
        g_b4f[c] = acc;
    } else {
        int c = e - OC;
        float acc = bd[c];
        for (int k = 0; k < UO; k++) acc += g_sh4[k] * Wd[k * FDIM + c];
        g_bdf[c] = acc;
    }
}

// ---------------- main: one CTA = two independent 8-row half-streams ---------
__global__ __launch_bounds__(NTHR, 1)
void lstm_ae_kernel(const float* __restrict__ x,
                    const float* __restrict__ b1,
                    float* __restrict__ out) {
    // per-half state buffers; stride HR=8 floats per unit (16B-aligned quads)
    __shared__ __align__(16) float h1s[2][UO * HR];
    __shared__ __align__(16) float h2s[2][UI * HR];
    __shared__ __align__(16) float h3s[2][UI * HR];
    __shared__ __align__(16) float h4s[2][UO * HR];
    __shared__ __align__(16) float xs[2][FDIM * HR];
    __shared__ float wds[UO * FDIM];
    __shared__ float bds[FDIM];

    const int tid  = threadIdx.x;
    const int half = tid >> 7;          // 0 or 1
    const int ltid = tid & 127;         // thread id within half
    const int bid  = 1 + half;          // named barrier id for this half
    const int row0 = blockIdx.x * BT + half * HR;

    float* h1 = h1s[half];
    float* h2 = h2s[half];
    float* h3 = h3s[half];
    float* h4 = h4s[half];
    float* xh = xs[half];

    // big mapping (512-col GEMMs z1/z4): u = ltid, all 8 rows (2 quads)
    const int ub = ltid;
    // small mapping (256-col GEMMs z2/z3): u = ltid&63, 4 rows
    const int us = ltid & 63;
    const int rs = (ltid >> 6) * 4;

    for (int i = tid; i < UO * HR * 2; i += NTHR) { h1s[0][i] = 0.f; h4s[0][i] = 0.f; }
    for (int i = tid; i < UI * HR * 2; i += NTHR) { h2s[0][i] = 0.f; h3s[0][i] = 0.f; }
    for (int i = tid; i < UO * FDIM; i += NTHR) wds[i] = g_Wdf[i];
    if (tid < FDIM) bds[tid] = g_bdf[tid];
    // x for t=0: ltid<64 handles 8 rows x 8 feats of this half
    if (ltid < HR * FDIM) {
        int r = ltid >> 3, k = ltid & 7;
        xh[k * HR + r] = x[(size_t)(row0 + r) * TDIM * FDIM + k];
    }

    float bb1[4], bb2[4], bb4[4];
#pragma unroll
    for (int g = 0; g < 4; g++) {
        bb1[g] = b1[g * UO + ub];
        bb2[g] = g_b2f[g * UI + us];
        bb4[g] = g_b4f[g * UO + ub];
    }

    float c1v[8], c4v[8], c2v[4], c3v[4];
#pragma unroll
    for (int i = 0; i < 8; i++) { c1v[i] = 0.f; c4v[i] = 0.f; }
#pragma unroll
    for (int i = 0; i < 4; i++) { c2v[i] = 0.f; c3v[i] = 0.f; }

    const float4* Wk1t = (const float4*)g_Wk1t;
    const float4* Wr1t = (const float4*)g_Wr1t;
    const float4* Wr2t = (const float4*)g_Wr2t;
    const float4* Wr3t = (const float4*)g_Wr3t;
    const float4* Wr4t = (const float4*)g_Wr4t;
    const float4* Wk2f = (const float4*)g_Wk2f;
    const float4* Wk3f = (const float4*)g_Wk3f;
    const float4* Wk4f = (const float4*)g_Wk4f;

    __syncthreads();   // only full-CTA barrier; halves are independent below

    // ================= Phase A: encoder (LSTM1 -> BN1 -> LSTM2) ==============
    for (int t = 0; t < TDIM; t++) {
        // z1 = x_t@Wk1 + b1 + h1@Wr1   (reads h1 OLD)
        float2 a1[4][4];
        init_acc<4>(a1, bb1);
#pragma unroll
        for (int k = 0; k < FDIM; k++)
            fma4q<2>(a1, Wk1t + k * UO + ub, (const float4*)(xh + k * HR));
#pragma unroll 8
        for (int k = 0; k < UO; k++)
            fma4q<2>(a1, Wr1t + k * UO + ub, (const float4*)(h1 + k * HR));

        // z2 recurrent part = h2@Wr2   (reads h2 OLD)
        float2 a2[4][2];
        init_acc<2>(a2, bb2);
#pragma unroll 8
        for (int k = 0; k < UI; k++)
            fma4q<1>(a2, Wr2t + k * UI + us, (const float4*)(h2 + k * HR + rs));

        barsync(bid);  // old-state reads complete (this half)

        gates_write<4>(a1, c1v, h1 + ub * HR);         // write h1 NEW (8 rows)
        if (t + 1 < TDIM && ltid < HR * FDIM) {        // prefetch x_{t+1}
            int r = ltid >> 3, k = ltid & 7;
            xh[k * HR + r] = x[(size_t)(row0 + r) * TDIM * FDIM + (t + 1) * FDIM + k];
        }
        barsync(bid);  // h1 NEW visible (this half)

        // z2 input part = h1_new @ Wk2f (BN1 folded)
#pragma unroll 8
        for (int k = 0; k < UO; k++)
            fma4q<1>(a2, Wk2f + k * UI + us, (const float4*)(h1 + k * HR + rs));

        gates_write<2>(a2, c2v, h2 + us * HR + rs);    // write h2 NEW
        barsync(bid);
    }

    // ============ transition: xz3 = enc_bn @ Wk3f + b3f (constant over t) ====
    float2 x3[4][2];
    {
        float bb3[4];
#pragma unroll
        for (int g = 0; g < 4; g++) bb3[g] = g_b3f[g * UI + us];
        init_acc<2>(x3, bb3);
#pragma unroll 8
        for (int k = 0; k < UI; k++)
            fma4q<1>(x3, Wk3f + k * UI + us, (const float4*)(h2 + k * HR + rs));
    }

    // ============ Phase B: decoder (LSTM3 -> BN3 -> LSTM4 -> BN4 -> Dense) ===
    const int dr = ltid >> 3, dc = ltid & 7;  // dense mapping (ltid < 64)
    for (int t = 0; t < TDIM; t++) {
        // z3 = xz3 + h3@Wr3  (reads h3 OLD)
        float2 a3[4][2];
#pragma unroll
        for (int g = 0; g < 4; g++) {
            a3[g][0] = x3[g][0]; a3[g][1] = x3[g][1];
        }
#pragma unroll 8
        for (int k = 0; k < UI; k++)
            fma4q<1>(a3, Wr3t + k * UI + us, (const float4*)(h3 + k * HR + rs));

        // z4 recurrent part = h4@Wr4  (reads h4 OLD)
        float2 a4[4][4];
        init_acc<4>(a4, bb4);
#pragma unroll 8
        for (int k = 0; k < UO; k++)
            fma4q<2>(a4, Wr4t + k * UO + ub, (const float4*)(h4 + k * HR));

        // dense head for step t-1 (reads h4 OLD = h4(t-1)), overlapped
        if (t > 0 && ltid < HR * FDIM) {
            float acc = bds[dc];
#pragma unroll 8
            for (int k = 0; k < UO; k++) acc += h4[k * HR + dr] * wds[k * FDIM + dc];
            out[(size_t)(row0 + dr) * TDIM * FDIM + (t - 1) * FDIM + dc] = acc;
        }

        barsync(bid);  // old-state reads complete (this half)

        gates_write<2>(a3, c3v, h3 + us * HR + rs);    // write h3 NEW
        barsync(bid);  // h3 NEW visible (this half)

        // z4 input part = h3_new @ Wk4f (BN3 folded)
#pragma unroll 8
        for (int k = 0; k < UI; k++)
            fma4q<2>(a4, Wk4f + k * UO + ub, (const float4*)(h3 + k * HR));

        gates_write<4>(a4, c4v, h4 + ub * HR);         // write h4 NEW
        barsync(bid);  // h4 NEW visible (this half)
    }

    // final dense head (t = T-1)
    if (ltid < HR * FDIM) {
        float acc = bds[dc];
#pragma unroll 8
        for (int k = 0; k < UO; k++) acc += h4[k * HR + dr] * wds[k * FDIM + dc];
        out[(size_t)(row0 + dr) * TDIM * FDIM + (TDIM - 1) * FDIM + dc] = acc;
    }
}

// ---------------- launch ------------------------------------------------------
extern "C" void kernel_launch(void* const* d_in, const int* in_sizes, int n_in,
                              void* d_out, int out_size) {
    const float* x   = (const float*)d_in[0];
    const float* Wk1 = (const float*)d_in[1];
    const float* Wr1 = (const float*)d_in[2];
    const float* b1  = (const float*)d_in[3];
    const float* g1  = (const float*)d_in[4];
    const float* be1 = (const float*)d_in[5];
    const float* m1  = (const float*)d_in[6];
    const float* v1  = (const float*)d_in[7];
    const float* Wk2 = (const float*)d_in[8];
    const float* Wr2 = (const float*)d_in[9];
    const float* b2  = (const float*)d_in[10];
    const float* g2  = (const float*)d_in[11];
    const float* be2 = (const float*)d_in[12];
    const float* m2  = (const float*)d_in[13];
    const float* v2  = (const float*)d_in[14];
    const float* Wk3 = (const float*)d_in[15];
    const float* Wr3 = (const float*)d_in[16];
    const float* b3  = (const float*)d_in[17];
    const float* g3  = (const float*)d_in[18];
    const float* be3 = (const float*)d_in[19];
    const float* m3  = (const float*)d_in[20];
    const float* v3  = (const float*)d_in[21];
    const float* Wk4 = (const float*)d_in[22];
    const float* Wr4 = (const float*)d_in[23];
    const float* b4  = (const float*)d_in[24];
    const float* g4  = (const float*)d_in[25];
    const float* be4 = (const float*)d_in[26];
    const float* m4  = (const float*)d_in[27];
    const float* v4  = (const float*)d_in[28];
    const float* Wd  = (const float*)d_in[29];
    const float* bd  = (const float*)d_in[30];

    prep_scales<<<1, 256>>>(g1, be1, m1, v1, g2, be2, m2, v2,
                            g3, be3, m3, v3, g4, be4, m4, v4);
    prep_fold<<<(NTOT + 255) / 256, 256>>>(Wk1, Wr1, Wr2, Wr3, Wr4,
                                           Wk2, b2, Wk3, b3, Wk4, b4, Wd, bd);
    lstm_ae_kernel<<<BDIM / BT, NTHR>>>(x, b1, (float*)d_out);
}

// round 5
// speedup vs baseline: 1.7720x; 1.1250x over previous
#include <cuda_runtime.h>

#define BDIM 2048
#define TDIM 128
#define FDIM 8
#define UO   128
#define UI   64
#define BT   16          // batch rows per CTA (two independent halves of 8)
#define HR   8           // rows per half
#define NTHR 256
#define BN_EPS 1e-3f

// ---------------- device scratch: BN-folded, gate-contiguous weights ---------
// Layout: Wt[(k*U + u)*4 + g]  ->  one float4 load gives all 4 gate weights.
__device__ float g_s1[UO], g_sh1[UO];
__device__ float g_s2[UI], g_sh2[UI];
__device__ float g_s3[UI], g_sh3[UI];
__device__ float g_s4[UO], g_sh4[UO];

__device__ __align__(16) float g_Wk1t[FDIM * UO * 4];
__device__ __align__(16) float g_Wr1t[UO * UO * 4];
__device__ __align__(16) float g_Wr2t[UI * UI * 4];
__device__ __align__(16) float g_Wr3t[UI * UI * 4];
__device__ __align__(16) float g_Wr4t[UO * UO * 4];
__device__ __align__(16) float g_Wk2f[UO * UI * 4];   // BN1 folded
__device__ __align__(16) float g_Wk3f[UI * UI * 4];   // BN2 folded
__device__ __align__(16) float g_Wk4f[UI * UO * 4];   // BN3 folded
__device__ float g_Wdf[UO * FDIM];                    // BN4 folded
__device__ float g_b2f[4 * UI];
__device__ float g_b3f[4 * UI];
__device__ float g_b4f[4 * UO];
__device__ float g_bdf[FDIM];

// ---------------- helpers ----------------------------------------------------
__device__ __forceinline__ float2 ffma2f(float2 a, float2 b, float2 c) {
    union U { float2 f; unsigned long long u; };
    U A, B, C, D;
    A.f = a; B.f = b; C.f = c;
    asm("fma.rn.f32x2 %0, %1, %2, %3;" : "=l"(D.u) : "l"(A.u), "l"(B.u), "l"(C.u));
    return D.f;
}

__device__ __forceinline__ void barsync(int id) {
    asm volatile("bar.sync %0, 128;" :: "r"(id) : "memory");
}

__device__ __forceinline__ float tanh_fast(float x) {
    float y;
    asm("tanh.approx.f32 %0, %1;" : "=f"(y) : "f"(x));
    return y;
}

// sigmoid(x) = 0.5*tanh(0.5x)+0.5 : 1 MUFU instead of 2
__device__ __forceinline__ float sigm(float x) {
    return fmaf(0.5f, tanh_fast(0.5f * x), 0.5f);
}

__device__ __forceinline__ float seluf(float x) {
    const float l = 1.0507009873554805f;
    const float a = 1.6732632423543772f;
    return x > 0.0f ? l * x : l * a * (__expf(x) - 1.0f);
}

__device__ __forceinline__ void gate_update(float zi, float zf, float zg, float zo,
                                            float& c, float& h) {
    float i = sigm(zi), f = sigm(zf), g = seluf(zg), o = sigm(zo);
    c = f * c + i * g;
    h = o * seluf(c);
}

// acc[4][4] covers 8 rows (2 quads); 16 FFMA2
__device__ __forceinline__ void acc8(float2 (&acc)[4][4], float4 w, float4 h0, float4 h1) {
    float ws[4] = {w.x, w.y, w.z, w.w};
#pragma unroll
    for (int g = 0; g < 4; g++) {
        float2 W = make_float2(ws[g], ws[g]);
        acc[g][0] = ffma2f(make_float2(h0.x, h0.y), W, acc[g][0]);
        acc[g][1] = ffma2f(make_float2(h0.z, h0.w), W, acc[g][1]);
        acc[g][2] = ffma2f(make_float2(h1.x, h1.y), W, acc[g][2]);
        acc[g][3] = ffma2f(make_float2(h1.z, h1.w), W, acc[g][3]);
    }
}

// acc[4][2] covers 4 rows (1 quad); 8 FFMA2
__device__ __forceinline__ void acc4(float2 (&acc)[4][2], float4 w, float4 h) {
    float ws[4] = {w.x, w.y, w.z, w.w};
#pragma unroll
    for (int g = 0; g < 4; g++) {
        float2 W = make_float2(ws[g], ws[g]);
        acc[g][0] = ffma2f(make_float2(h.x, h.y), W, acc[g][0]);
        acc[g][1] = ffma2f(make_float2(h.z, h.w), W, acc[g][1]);
    }
}

template <int NP>
__device__ __forceinline__ void init_acc(float2 (&acc)[4][NP], const float b[4]) {
#pragma unroll
    for (int g = 0; g < 4; g++)
#pragma unroll
        for (int p = 0; p < NP; p++) acc[g][p] = make_float2(b[g], b[g]);
}

template <int NP>
__device__ __forceinline__ void gates_write(float2 (&acc)[4][NP], float* cvec, float* hrow) {
#pragma unroll
    for (int p = 0; p < NP; p++) {
        {
            float c = cvec[2 * p], h;
            gate_update(acc[0][p].x, acc[1][p].x, acc[2][p].x, acc[3][p].x, c, h);
            cvec[2 * p] = c; hrow[2 * p] = h;
        }
        {
            float c = cvec[2 * p + 1], h;
            gate_update(acc[0][p].y, acc[1][p].y, acc[2][p].y, acc[3][p].y, c, h);
            cvec[2 * p + 1] = c; hrow[2 * p + 1] = h;
        }
    }
}

// ---------------- prep 1: BN scale/shift vectors ------------------------------
__global__ void prep_scales(const float* __restrict__ g1, const float* __restrict__ be1,
                            const float* __restrict__ m1, const float* __restrict__ v1,
                            const float* __restrict__ g2, const float* __restrict__ be2,
                            const float* __restrict__ m2, const float* __restrict__ v2,
                            const float* __restrict__ g3, const float* __restrict__ be3,
                            const float* __restrict__ m3, const float* __restrict__ v3,
                            const float* __restrict__ g4, const float* __restrict__ be4,
                            const float* __restrict__ m4, const float* __restrict__ v4) {
    int i = threadIdx.x;
    if (i < UO) {
        float s = g1[i] * rsqrtf(v1[i] + BN_EPS);
        g_s1[i] = s; g_sh1[i] = be1[i] - m1[i] * s;
        s = g4[i] * rsqrtf(v4[i] + BN_EPS);
        g_s4[i] = s; g_sh4[i] = be4[i] - m4[i] * s;
    }
    if (i < UI) {
        float s = g2[i] * rsqrtf(v2[i] + BN_EPS);
        g_s2[i] = s; g_sh2[i] = be2[i] - m2[i] * s;
        s = g3[i] * rsqrtf(v3[i] + BN_EPS);
        g_s3[i] = s; g_sh3[i] = be3[i] - m3[i] * s;
    }
}

// ---------------- prep 2: transpose to gate-contiguous + fold BN --------------
#define N_WK1T  (FDIM * UO * 4)
#define N_WR1T  (UO * UO * 4)
#define N_WR2T  (UI * UI * 4)
#define N_WR3T  (UI * UI * 4)
#define N_WR4T  (UO * UO * 4)
#define N_WK2F  (UO * UI * 4)
#define N_WK3F  (UI * UI * 4)
#define N_WK4F  (UI * UO * 4)
#define N_WDF   (UO * FDIM)
#define O1 N_WK1T
#define O2 (O1 + N_WR1T)
#define O3 (O2 + N_WR2T)
#define O4 (O3 + N_WR3T)
#define O5 (O4 + N_WR4T)
#define O6 (O5 + N_WK2F)
#define O7 (O6 + N_WK3F)
#define O8 (O7 + N_WK4F)
#define O9 (O8 + N_WDF)
#define OA (O9 + 4 * UI)
#define OB (OA + 4 * UI)
#define OC (OB + 4 * UO)
#define OD (OC + FDIM)
#define NTOT OD

__global__ void prep_fold(const float* __restrict__ Wk1, const float* __restrict__ Wr1,
                          const float* __restrict__ Wr2, const float* __restrict__ Wr3,
                          const float* __restrict__ Wr4,
                          const float* __restrict__ Wk2, const float* __restrict__ b2,
                          const float* __restrict__ Wk3, const float* __restrict__ b3,
                          const float* __restrict__ Wk4, const float* __restrict__ b4,
                          const float* __restrict__ Wd,  const float* __restrict__ bd) {
    int e = blockIdx.x * blockDim.x + threadIdx.x;
    if (e >= NTOT) return;
    if (e < O1) {
        int g = e & 3, u = (e >> 2) & (UO - 1), k = e >> 9;
        g_Wk1t[e] = Wk1[k * 4 * UO + g * UO + u];
    } else if (e < O2) {
        int i = e - O1;
        int g = i & 3, u = (i >> 2) & (UO - 1), k = i >> 9;
        g_Wr1t[i] = Wr1[k * 4 * UO + g * UO + u];
    } else if (e < O3) {
        int i = e - O2;
        int g = i & 3, u = (i >> 2) & (UI - 1), k = i >> 8;
        g_Wr2t[i] = Wr2[k * 4 * UI + g * UI + u];
    } else if (e < O4) {
        int i = e - O3;
        int g = i & 3, u = (i >> 2) & (UI - 1), k = i >> 8;
        g_Wr3t[i] = Wr3[k * 4 * UI + g * UI + u];
    } else if (e < O5) {
        int i = e - O4;
        int g = i & 3, u = (i >> 2) & (UO - 1), k = i >> 9;
        g_Wr4t[i] = Wr4[k * 4 * UO + g * UO + u];
    } else if (e < O6) {
        int i = e - O5;
        int g = i & 3, u = (i >> 2) & (UI - 1), k = i >> 8;
        g_Wk2f[i] = g_s1[k] * Wk2[k * 4 * UI + g * UI + u];
    } else if (e < O7) {
        int i = e - O6;
        int g = i & 3, u = (i >> 2) & (UI - 1), k = i >> 8;
        g_Wk3f[i] = g_s2[k] * Wk3[k * 4 * UI + g * UI + u];
    } else if (e < O8) {
        int i = e - O7;
        int g = i & 3, u = (i >> 2) & (UO - 1), k = i >> 9;
        g_Wk4f[i] = g_s3[k] * Wk4[k * 4 * UO + g * UO + u];
    } else if (e < O9) {
        int i = e - O8;
        int k = i >> 3;
        g_Wdf[i] = g_s4[k] * Wd[i];
    } else if (e < OA) {
        int c = e - O9;
        float acc = b2[c];
        for (int k = 0; k < UO; k++) acc += g_sh1[k] * Wk2[k * 4 * UI + c];
        g_b2f[c] = acc;
    } else if (e < OB) {
        int c = e - OA;
        float acc = b3[c];
        for (int k = 0; k < UI; k++) acc += g_sh2[k] * Wk3[k * 4 * UI + c];
        g_b3f[c] = acc;
    } else if (e < OC) {
        int c = e - OB;
        float acc = b4[c];
        for (int k = 0; k < UI; k++) acc += g_sh3[k] * Wk4[k * 4 * UO + c];
        g_b4f[c] = acc;
    } else {
        int c = e - OC;
        float acc = bd[c];
        for (int k = 0; k < UO; k++) acc += g_sh4[k] * Wd[k * FDIM + c];
        g_bdf[c] = acc;
    }
}

// ---------------- main: pipelined two-layer fusion, two half-streams ---------
__global__ __launch_bounds__(NTHR, 1)
void lstm_ae_kernel(const float* __restrict__ x,
                    const float* __restrict__ b1,
                    float* __restrict__ out) {
    __shared__ __align__(16) float h1s[2][UO * HR];
    __shared__ __align__(16) float h2s[2][UI * HR];
    __shared__ __align__(16) float h3s[2][UI * HR];
    __shared__ __align__(16) float h4s[2][UO * HR];
    __shared__ __align__(16) float xs[2][FDIM * HR];
    __shared__ float wds[UO * FDIM];
    __shared__ float bds[FDIM];

    const int tid  = threadIdx.x;
    const int half = tid >> 7;
    const int ltid = tid & 127;
    const int bid  = 1 + half;
    const int row0 = blockIdx.x * BT + half * HR;

    float* h1 = h1s[half];
    float* h2 = h2s[half];
    float* h3 = h3s[half];
    float* h4 = h4s[half];
    float* xh = xs[half];

    const int ub = ltid;                 // big GEMMs: u-quad, all 8 rows
    const int us = ltid & 63;            // small GEMMs: u-quad
    const int rs = (ltid >> 6) * 4;      // small GEMMs: row-quad offset (0 or 4)

    for (int i = tid; i < UO * HR * 2; i += NTHR) { h1s[0][i] = 0.f; h4s[0][i] = 0.f; }
    for (int i = tid; i < UI * HR * 2; i += NTHR) { h2s[0][i] = 0.f; h3s[0][i] = 0.f; }
    for (int i = tid; i < UO * FDIM; i += NTHR) wds[i] = g_Wdf[i];
    if (tid < FDIM) bds[tid] = g_bdf[tid];
    if (ltid < HR * FDIM) {
        int r = ltid >> 3, k = ltid & 7;
        xh[k * HR + r] = x[(size_t)(row0 + r) * TDIM * FDIM + k];
    }

    float bb1[4], bb2[4], bb4[4];
#pragma unroll
    for (int g = 0; g < 4; g++) {
        bb1[g] = b1[g * UO + ub];
        bb2[g] = g_b2f[g * UI + us];
        bb4[g] = g_b4f[g * UO + ub];
    }

    float c1v[8], c4v[8], c2v[4], c3v[4];
#pragma unroll
    for (int i = 0; i < 8; i++) { c1v[i] = 0.f; c4v[i] = 0.f; }
#pragma unroll
    for (int i = 0; i < 4; i++) { c2v[i] = 0.f; c3v[i] = 0.f; }

    const float4* Wk1t = (const float4*)g_Wk1t;
    const float4* Wr1t = (const float4*)g_Wr1t;
    const float4* Wr2t = (const float4*)g_Wr2t;
    const float4* Wr3t = (const float4*)g_Wr3t;
    const float4* Wr4t = (const float4*)g_Wr4t;
    const float4* Wk2f = (const float4*)g_Wk2f;
    const float4* Wk3f = (const float4*)g_Wk3f;
    const float4* Wk4f = (const float4*)g_Wk4f;

    __syncthreads();

    // ========== Phase A: LSTM1(t) fused with LSTM2(t-1), pipelined ==========
    // Loop-top invariant: h1s = h1(t-1), h2s = h2(t-2), xh = x(t).
    for (int t = 0; t < TDIM; t++) {
        float2 a1[4][4];
        init_acc<4>(a1, bb1);
        float2 a2[4][2];
        init_acc<2>(a2, bb2);

        // z1 input part: x(t) @ Wk1
#pragma unroll
        for (int k = 0; k < FDIM; k++) {
            float4 w = __ldg(Wk1t + k * UO + ub);
            const float4* xq = (const float4*)(xh + k * HR);
            acc8(a1, w, xq[0], xq[1]);
        }
        // fused k<64: Wr1·h1(t-1), Wk2f·h1(t-1), Wr2·h2(t-2)
#pragma unroll 4
        for (int k = 0; k < UI; k++) {
            float4 w1 = __ldg(Wr1t + k * UO + ub);
            float4 w2 = __ldg(Wk2f + k * UI + us);
            float4 wr = __ldg(Wr2t + k * UI + us);
            const float4* hq = (const float4*)(h1 + k * HR);
            float4 h1a = hq[0], h1b = hq[1];
            float4 h1sel = *(const float4*)(h1 + k * HR + rs);
            float4 h2q  = *(const float4*)(h2 + k * HR + rs);
            acc8(a1, w1, h1a, h1b);
            acc4(a2, w2, h1sel);
            acc4(a2, wr, h2q);
        }
        // k 64..127: Wr1·h1, Wk2f·h1
#pragma unroll 4
        for (int k = UI; k < UO; k++) {
            float4 w1 = __ldg(Wr1t + k * UO + ub);
            float4 w2 = __ldg(Wk2f + k * UI + us);
            const float4* hq = (const float4*)(h1 + k * HR);
            float4 h1a = hq[0], h1b = hq[1];
            float4 h1sel = *(const float4*)(h1 + k * HR + rs);
            acc8(a1, w1, h1a, h1b);
            acc4(a2, w2, h1sel);
        }

        barsync(bid);  // old-state reads complete

        gates_write<4>(a1, c1v, h1 + ub * HR);                  // h1(t)
        if (t > 0) gates_write<2>(a2, c2v, h2 + us * HR + rs);  // h2(t-1)
        if (t + 1 < TDIM && ltid < HR * FDIM) {                 // x(t+1)
            int r = ltid >> 3, k = ltid & 7;
            xh[k * HR + r] = x[(size_t)(row0 + r) * TDIM * FDIM + (t + 1) * FDIM + k];
        }
        barsync(bid);  // new state visible
    }

    // epilogue A: h2(127) from h1(127), h2(126)
    {
        float2 a2[4][2];
        init_acc<2>(a2, bb2);
#pragma unroll 4
        for (int k = 0; k < UI; k++) {
            float4 w2 = __ldg(Wk2f + k * UI + us);
            float4 wr = __ldg(Wr2t + k * UI + us);
            float4 h1sel = *(const float4*)(h1 + k * HR + rs);
            float4 h2q  = *(const float4*)(h2 + k * HR + rs);
            acc4(a2, w2, h1sel);
            acc4(a2, wr, h2q);
        }
#pragma unroll 4
        for (int k = UI; k < UO; k++) {
            float4 w2 = __ldg(Wk2f + k * UI + us);
            float4 h1sel = *(const float4*)(h1 + k * HR + rs);
            acc4(a2, w2, h1sel);
        }
        barsync(bid);
        gates_write<2>(a2, c2v, h2 + us * HR + rs);  // h2(127)
        barsync(bid);
    }

    // ===== transition: xz3 = enc_bn @ Wk3f + b3f (constant over t) ==========
    float2 x3[4][2];
    {
        float bb3[4];
#pragma unroll
        for (int g = 0; g < 4; g++) bb3[g] = g_b3f[g * UI + us];
        init_acc<2>(x3, bb3);
#pragma unroll 4
        for (int k = 0; k < UI; k++) {
            float4 w = __ldg(Wk3f + k * UI + us);
            float4 hq = *(const float4*)(h2 + k * HR + rs);
            acc4(x3, w, hq);
        }
    }

    // ========== Phase B: LSTM3(t) fused with LSTM4(t-1) + Dense(t-2) ========
    // Loop-top invariant: h3s = h3(t-1), h4s = h4(t-2).
    const int dr = ltid >> 3, dc = ltid & 7;
    for (int t = 0; t < TDIM; t++) {
        float2 a3[4][2];
#pragma unroll
        for (int g = 0; g < 4; g++) { a3[g][0] = x3[g][0]; a3[g][1] = x3[g][1]; }
        float2 a4[4][4];
        init_acc<4>(a4, bb4);

        // fused k<64: Wr4·h4(t-2), Wk4f·h3(t-1), Wr3·h3(t-1)
#pragma unroll 4
        for (int k = 0; k < UI; k++) {
            float4 w4 = __ldg(Wr4t + k * UO + ub);
            float4 wk = __ldg(Wk4f + k * UO + ub);
            float4 w3 = __ldg(Wr3t + k * UI + us);
            const float4* h4q = (const float4*)(h4 + k * HR);
            float4 h4a = h4q[0], h4b = h4q[1];
            const float4* h3q = (const float4*)(h3 + k * HR);
            float4 h3a = h3q[0], h3b = h3q[1];
            float4 h3sel = *(const float4*)(h3 + k * HR + rs);
            acc8(a4, w4, h4a, h4b);
            acc8(a4, wk, h3a, h3b);
            acc4(a3, w3, h3sel);
        }
        // k 64..127: Wr4·h4 only
#pragma unroll 4
        for (int k = UI; k < UO; k++) {
            float4 w4 = __ldg(Wr4t + k * UO + ub);
            const float4* h4q = (const float4*)(h4 + k * HR);
            acc8(a4, w4, h4q[0], h4q[1]);
        }

        // dense head out(t-2) from h4(t-2), overlapped with GEMM reads
        if (t >= 2 && ltid < HR * FDIM) {
            float acc = bds[dc];
#pragma unroll 8
            for (int k = 0; k < UO; k++) acc += h4[k * HR + dr] * wds[k * FDIM + dc];
            out[(size_t)(row0 + dr) * TDIM * FDIM + (t - 2) * FDIM + dc] = acc;
        }

        barsync(bid);  // old-state reads complete

        gates_write<2>(a3, c3v, h3 + us * HR + rs);             // h3(t)
        if (t > 0) gates_write<4>(a4, c4v, h4 + ub * HR);       // h4(t-1)
        barsync(bid);  // new state visible
    }

    // epilogue B: h4(127) from h4(126), h3(127); dense out(126), out(127)
    {
        float2 a4[4][4];
        init_acc<4>(a4, bb4);
#pragma unroll 4
        for (int k = 0; k < UI; k++) {
            float4 w4 = __ldg(Wr4t + k * UO + ub);
            float4 wk = __ldg(Wk4f + k * UO + ub);
            const float4* h4q = (const float4*)(h4 + k * HR);
            const float4* h3q = (const float4*)(h3 + k * HR);
            acc8(a4, w4, h4q[0], h4q[1]);
            acc8(a4, wk, h3q[0], h3q[1]);
        }
#pragma unroll 4
        for (int k = UI; k < UO; k++) {
            float4 w4 = __ldg(Wr4t + k * UO + ub);
            const float4* h4q = (const float4*)(h4 + k * HR);
            acc8(a4, w4, h4q[0], h4q[1]);
        }
        if (ltid < HR * FDIM) {  // out(126) from h4(126)
            float acc = bds[dc];
#pragma unroll 8
            for (int k = 0; k < UO; k++) acc += h4[k * HR + dr] * wds[k * FDIM + dc];
            out[(size_t)(row0 + dr) * TDIM * FDIM + 126 * FDIM + dc] = acc;
        }
        barsync(bid);
        gates_write<4>(a4, c4v, h4 + ub * HR);  // h4(127)
        barsync(bid);
        if (ltid < HR * FDIM) {  // out(127)
            float acc = bds[dc];
#pragma unroll 8
            for (int k = 0; k < UO; k++) acc += h4[k * HR + dr] * wds[k * FDIM + dc];
            out[(size_t)(row0 + dr) * TDIM * FDIM + 127 * FDIM + dc] = acc;
        }
    }
}

// ---------------- launch ------------------------------------------------------
extern "C" void kernel_launch(void* const* d_in, const int* in_sizes, int n_in,
                              void* d_out, int out_size) {
    const float* x   = (const float*)d_in[0];
    const float* Wk1 = (const float*)d_in[1];
    const float* Wr1 = (const float*)d_in[2];
    const float* b1  = (const float*)d_in[3];
    const float* g1  = (const float*)d_in[4];
    const float* be1 = (const float*)d_in[5];
    const float* m1  = (const float*)d_in[6];
    const float* v1  = (const float*)d_in[7];
    const float* Wk2 = (const float*)d_in[8];
    const float* Wr2 = (const float*)d_in[9];
    const float* b2  = (const float*)d_in[10];
    const float* g2  = (const float*)d_in[11];
    const float* be2 = (const float*)d_in[12];
    const float* m2  = (const float*)d_in[13];
    const float* v2  = (const float*)d_in[14];
    const float* Wk3 = (const float*)d_in[15];
    const float* Wr3 = (const float*)d_in[16];
    const float* b3  = (const float*)d_in[17];
    const float* g3  = (const float*)d_in[18];
    const float* be3 = (const float*)d_in[19];
    const float* m3  = (const float*)d_in[20];
    const float* v3  = (const float*)d_in[21];
    const float* Wk4 = (const float*)d_in[22];
    const float* Wr4 = (const float*)d_in[23];
    const float* b4  = (const float*)d_in[24];
    const float* g4  = (const float*)d_in[25];
    const float* be4 = (const float*)d_in[26];
    const float* m4  = (const float*)d_in[27];
    const float* v4  = (const float*)d_in[28];
    const float* Wd  = (const float*)d_in[29];
    const float* bd  = (const float*)d_in[30];

    prep_scales<<<1, 256>>>(g1, be1, m1, v1, g2, be2, m2, v2,
                            g3, be3, m3, v3, g4, be4, m4, v4);
    prep_fold<<<(NTOT + 255) / 256, 256>>>(Wk1, Wr1, Wr2, Wr3, Wr4,
                                           Wk2, b2, Wk3, b3, Wk4, b4, Wd, bd);
    lstm_ae_kernel<<<BDIM / BT, NTHR>>>(x, b1, (float*)d_out);
}

// round 6
// speedup vs baseline: 1.8806x; 1.0612x over previous
#include <cuda_runtime.h>

#define BDIM 2048
#define TDIM 128
#define FDIM 8
#define UO   128
#define UI   64
#define BT   16          // batch rows per CTA (two independent halves of 8)
#define HR   8           // rows per half
#define NTHR 256
#define BN_EPS 1e-3f

// ---------------- device scratch: BN-folded, gate-contiguous weights ---------
// Layout: Wt[(k*U + u)*4 + g]  ->  one float4 load gives all 4 gate weights.
__device__ __align__(16) float g_Wk1t[FDIM * UO * 4];
__device__ __align__(16) float g_Wr1t[UO * UO * 4];
__device__ __align__(16) float g_Wr2t[UI * UI * 4];
__device__ __align__(16) float g_Wr3t[UI * UI * 4];
__device__ __align__(16) float g_Wr4t[UO * UO * 4];
__device__ __align__(16) float g_Wk2f[UO * UI * 4];   // BN1 folded
__device__ __align__(16) float g_Wk3f[UI * UI * 4];   // BN2 folded
__device__ __align__(16) float g_Wk4f[UI * UO * 4];   // BN3 folded
__device__ __align__(16) float g_Wdf[UO * FDIM];      // BN4 folded
__device__ float g_b2f[4 * UI];
__device__ float g_b3f[4 * UI];
__device__ float g_b4f[4 * UO];
__device__ float g_bdf[FDIM];

// ---------------- dynamic smem layout (floats) --------------------------------
#define SM_WBIG   0                            // 32768: Wk2f (A) / Wk4f (B)
#define SM_WSMALL 32768                        // 16384: Wr2t (A) / Wr3t (B)
#define SM_H1     (SM_WSMALL + 16384)          // 2048
#define SM_H2     (SM_H1 + 2048)               // 1024
#define SM_H3     (SM_H2 + 1024)               // 1024
#define SM_H4     (SM_H3 + 1024)               // 2048
#define SM_XS     (SM_H4 + 2048)               // 128
#define SM_WDS    (SM_XS + 128)                // 1024
#define SM_BDS    (SM_WDS + 1024)              // 8
#define SM_TOTAL  (SM_BDS + 8)                 // 56456 floats = 225824 B
#define SMEM_BYTES (SM_TOTAL * 4)

// ---------------- helpers ----------------------------------------------------
__device__ __forceinline__ float2 ffma2f(float2 a, float2 b, float2 c) {
    union U { float2 f; unsigned long long u; };
    U A, B, C, D;
    A.f = a; B.f = b; C.f = c;
    asm("fma.rn.f32x2 %0, %1, %2, %3;" : "=l"(D.u) : "l"(A.u), "l"(B.u), "l"(C.u));
    return D.f;
}

__device__ __forceinline__ void barsync(int id) {
    asm volatile("bar.sync %0, 128;" :: "r"(id) : "memory");
}

__device__ __forceinline__ float tanh_fast(float x) {
    float y;
    asm("tanh.approx.f32 %0, %1;" : "=f"(y) : "f"(x));
    return y;
}

// sigmoid(x) = 0.5*tanh(0.5x)+0.5 : 1 MUFU instead of 2
__device__ __forceinline__ float sigm(float x) {
    return fmaf(0.5f, tanh_fast(0.5f * x), 0.5f);
}

__device__ __forceinline__ float seluf(float x) {
    const float l = 1.0507009873554805f;
    const float a = 1.6732632423543772f;
    return x > 0.0f ? l * x : l * a * (__expf(x) - 1.0f);
}

__device__ __forceinline__ void gate_update(float zi, float zf, float zg, float zo,
                                            float& c, float& h) {
    float i = sigm(zi), f = sigm(zf), g = seluf(zg), o = sigm(zo);
    c = f * c + i * g;
    h = o * seluf(c);
}

// acc[4][4] covers 8 rows (2 quads); 16 FFMA2
__device__ __forceinline__ void acc8(float2 (&acc)[4][4], float4 w, float4 h0, float4 h1) {
    float ws[4] = {w.x, w.y, w.z, w.w};
#pragma unroll
    for (int g = 0; g < 4; g++) {
        float2 W = make_float2(ws[g], ws[g]);
        acc[g][0] = ffma2f(make_float2(h0.x, h0.y), W, acc[g][0]);
        acc[g][1] = ffma2f(make_float2(h0.z, h0.w), W, acc[g][1]);
        acc[g][2] = ffma2f(make_float2(h1.x, h1.y), W, acc[g][2]);
        acc[g][3] = ffma2f(make_float2(h1.z, h1.w), W, acc[g][3]);
    }
}

// acc[4][2] covers 4 rows (1 quad); 8 FFMA2
__device__ __forceinline__ void acc4(float2 (&acc)[4][2], float4 w, float4 h) {
    float ws[4] = {w.x, w.y, w.z, w.w};
#pragma unroll
    for (int g = 0; g < 4; g++) {
        float2 W = make_float2(ws[g], ws[g]);
        acc[g][0] = ffma2f(make_float2(h.x, h.y), W, acc[g][0]);
        acc[g][1] = ffma2f(make_float2(h.z, h.w), W, acc[g][1]);
    }
}

template <int NP>
__device__ __forceinline__ void init_acc(float2 (&acc)[4][NP], const float b[4]) {
#pragma unroll
    for (int g = 0; g < 4; g++)
#pragma unroll
        for (int p = 0; p < NP; p++) acc[g][p] = make_float2(b[g], b[g]);
}

template <int NP>
__device__ __forceinline__ void gates_write(float2 (&acc)[4][NP], float* cvec, float* hrow) {
#pragma unroll
    for (int p = 0; p < NP; p++) {
        {
            float c = cvec[2 * p], h;
            gate_update(acc[0][p].x, acc[1][p].x, acc[2][p].x, acc[3][p].x, c, h);
            cvec[2 * p] = c; hrow[2 * p] = h;
        }
        {
            float c = cvec[2 * p + 1], h;
            gate_update(acc[0][p].y, acc[1][p].y, acc[2][p].y, acc[3][p].y, c, h);
            cvec[2 * p + 1] = c; hrow[2 * p + 1] = h;
        }
    }
}

// ---------------- single merged prep kernel -----------------------------------
#define N_WK1T  (FDIM * UO * 4)
#define N_WR1T  (UO * UO * 4)
#define N_WR2T  (UI * UI * 4)
#define N_WR3T  (UI * UI * 4)
#define N_WR4T  (UO * UO * 4)
#define N_WK2F  (UO * UI * 4)
#define N_WK3F  (UI * UI * 4)
#define N_WK4F  (UI * UO * 4)
#define N_WDF   (UO * FDIM)
#define O1 N_WK1T
#define O2 (O1 + N_WR1T)
#define O3 (O2 + N_WR2T)
#define O4 (O3 + N_WR3T)
#define O5 (O4 + N_WR4T)
#define O6 (O5 + N_WK2F)
#define O7 (O6 + N_WK3F)
#define O8 (O7 + N_WK4F)
#define O9 (O8 + N_WDF)
#define OA (O9 + 4 * UI)
#define OB (OA + 4 * UI)
#define OC (OB + 4 * UO)
#define OD (OC + FDIM)
#define NTOT OD

__device__ __forceinline__ float bn_s(const float* g, const float* v, int k) {
    return g[k] * rsqrtf(v[k] + BN_EPS);
}
__device__ __forceinline__ float bn_sh(const float* g, const float* be, const float* m,
                                       const float* v, int k) {
    float s = g[k] * rsqrtf(v[k] + BN_EPS);
    return be[k] - m[k] * s;
}

__global__ void prep_all(const float* __restrict__ Wk1, const float* __restrict__ Wr1,
                         const float* __restrict__ Wr2, const float* __restrict__ Wr3,
                         const float* __restrict__ Wr4,
                         const float* __restrict__ Wk2, const float* __restrict__ b2,
                         const float* __restrict__ Wk3, const float* __restrict__ b3,
                         const float* __restrict__ Wk4, const float* __restrict__ b4,
                         const float* __restrict__ Wd,  const float* __restrict__ bd,
                         const float* __restrict__ g1, const float* __restrict__ be1,
                         const float* __restrict__ m1, const float* __restrict__ v1,
                         const float* __restrict__ g2, const float* __restrict__ be2,
                         const float* __restrict__ m2, const float* __restrict__ v2,
                         const float* __restrict__ g3, const float* __restrict__ be3,
                         const float* __restrict__ m3, const float* __restrict__ v3,
                         const float* __restrict__ g4, const float* __restrict__ be4,
                         const float* __restrict__ m4, const float* __restrict__ v4) {
    int e = blockIdx.x * blockDim.x + threadIdx.x;
    if (e >= NTOT) return;
    if (e < O1) {
        int g = e & 3, u = (e >> 2) & (UO - 1), k = e >> 9;
        g_Wk1t[e] = Wk1[k * 4 * UO + g * UO + u];
    } else if (e < O2) {
        int i = e - O1;
        int g = i & 3, u = (i >> 2) & (UO - 1), k = i >> 9;
        g_Wr1t[i] = Wr1[k * 4 * UO + g * UO + u];
    } else if (e < O3) {
        int i = e - O2;
        int g = i & 3, u = (i >> 2) & (UI - 1), k = i >> 8;
        g_Wr2t[i] = Wr2[k * 4 * UI + g * UI + u];
    } else if (e < O4) {
        int i = e - O3;
        int g = i & 3, u = (i >> 2) & (UI - 1), k = i >> 8;
        g_Wr3t[i] = Wr3[k * 4 * UI + g * UI + u];
    } else if (e < O5) {
        int i = e - O4;
        int g = i & 3, u = (i >> 2) & (UO - 1), k = i >> 9;
        g_Wr4t[i] = Wr4[k * 4 * UO + g * UO + u];
    } else if (e < O6) {
        int i = e - O5;
        int g = i & 3, u = (i >> 2) & (UI - 1), k = i >> 8;
        g_Wk2f[i] = bn_s(g1, v1, k) * Wk2[k * 4 * UI + g * UI + u];
    } else if (e < O7) {
        int i = e - O6;
        int g = i & 3, u = (i >> 2) & (UI - 1), k = i >> 8;
        g_Wk3f[i] = bn_s(g2, v2, k) * Wk3[k * 4 * UI + g * UI + u];
    } else if (e < O8) {
        int i = e - O7;
        int g = i & 3, u = (i >> 2) & (UO - 1), k = i >> 9;
        g_Wk4f[i] = bn_s(g3, v3, k) * Wk4[k * 4 * UO + g * UO + u];
    } else if (e < O9) {
        int i = e - O8;
        int k = i >> 3;
        g_Wdf[i] = bn_s(g4, v4, k) * Wd[i];
    } else if (e < OA) {
        int c = e - O9;
        float acc = b2[c];
        for (int k = 0; k < UO; k++) acc += bn_sh(g1, be1, m1, v1, k) * Wk2[k * 4 * UI + c];
        g_b2f[c] = acc;
    } else if (e < OB) {
        int c = e - OA;
        float acc = b3[c];
        for (int k = 0; k < UI; k++) acc += bn_sh(g2, be2, m2, v2, k) * Wk3[k * 4 * UI + c];
        g_b3f[c] = acc;
    } else if (e < OC) {
        int c = e - OB;
        float acc = b4[c];
        for (int k = 0; k < UI; k++) acc += bn_sh(g3, be3, m3, v3, k) * Wk4[k * 4 * UO + c];
        g_b4f[c] = acc;
    } else {
        int c = e - OC;
        float acc = bd[c];
        for (int k = 0; k < UO; k++) acc += bn_sh(g4, be4, m4, v4, k) * Wd[k * FDIM + c];
        g_bdf[c] = acc;
    }
}

// ---------------- main: pipelined fusion + smem-resident small-GEMM weights ---
__global__ __launch_bounds__(NTHR, 1)
void lstm_ae_kernel(const float* __restrict__ x,
                    const float* __restrict__ b1,
                    float* __restrict__ out) {
    extern __shared__ __align__(16) float sm[];
    float* wbig   = sm + SM_WBIG;     // Wk2f (phase A) / Wk4f (phase B)
    float* wsmall = sm + SM_WSMALL;   // Wr2t (phase A) / Wr3t (phase B)
    float* wds    = sm + SM_WDS;
    float* bds    = sm + SM_BDS;

    const int tid  = threadIdx.x;
    const int half = tid >> 7;
    const int ltid = tid & 127;
    const int bid  = 1 + half;
    const int row0 = blockIdx.x * BT + half * HR;

    float* h1 = sm + SM_H1 + half * (UO * HR);
    float* h2 = sm + SM_H2 + half * (UI * HR);
    float* h3 = sm + SM_H3 + half * (UI * HR);
    float* h4 = sm + SM_H4 + half * (UO * HR);
    float* xh = sm + SM_XS + half * (FDIM * HR);

    const int ub = ltid;                 // big GEMMs: u-quad, all 8 rows
    const int us = ltid & 63;            // small GEMMs: u-quad
    const int rs = (ltid >> 6) * 4;      // small GEMMs: row-quad offset (0 or 4)

    // zero state, load dense weights, stage phase-A smem weights
    for (int i = tid; i < UO * HR * 2; i += NTHR) { sm[SM_H1 + i] = 0.f; sm[SM_H4 + i] = 0.f; }
    for (int i = tid; i < UI * HR * 2; i += NTHR) { sm[SM_H2 + i] = 0.f; sm[SM_H3 + i] = 0.f; }
    for (int i = tid; i < UO * FDIM; i += NTHR) wds[i] = g_Wdf[i];
    if (tid < FDIM) bds[tid] = g_bdf[tid];
    if (ltid < HR * FDIM) {
        int r = ltid >> 3, k = ltid & 7;
        xh[k * HR + r] = x[(size_t)(row0 + r) * TDIM * FDIM + k];
    }
    {
        float4* d1 = (float4*)wbig;
        const float4* s1 = (const float4*)g_Wk2f;
        for (int i = tid; i < N_WK2F / 4; i += NTHR) d1[i] = s1[i];
        float4* d2 = (float4*)wsmall;
        const float4* s2 = (const float4*)g_Wr2t;
        for (int i = tid; i < N_WR2T / 4; i += NTHR) d2[i] = s2[i];
    }

    float bb1[4], bb2[4], bb4[4];
#pragma unroll
    for (int g = 0; g < 4; g++) {
        bb1[g] = b1[g * UO + ub];
        bb2[g] = g_b2f[g * UI + us];
        bb4[g] = g_b4f[g * UO + ub];
    }

    float c1v[8], c4v[8], c2v[4], c3v[4];
#pragma unroll
    for (int i = 0; i < 8; i++) { c1v[i] = 0.f; c4v[i] = 0.f; }
#pragma unroll
    for (int i = 0; i < 4; i++) { c2v[i] = 0.f; c3v[i] = 0.f; }

    const float4* Wk1t = (const float4*)g_Wk1t;
    const float4* Wr1t = (const float4*)g_Wr1t;
    const float4* Wr4t = (const float4*)g_Wr4t;
    const float4* Wk3f = (const float4*)g_Wk3f;
    const float4* wbig4   = (const float4*)wbig;
    const float4* wsmall4 = (const float4*)wsmall;

    __syncthreads();

    // ========== Phase A: LSTM1(t) fused with LSTM2(t-1), pipelined ==========
    // Loop-top invariant: h1 = h1(t-1), h2 = h2(t-2), xh = x(t).
    for (int t = 0; t < TDIM; t++) {
        float2 a1[4][4];
        init_acc<4>(a1, bb1);
        float2 a2[4][2];
        init_acc<2>(a2, bb2);

        // z1 input part: x(t) @ Wk1
#pragma unroll
        for (int k = 0; k < FDIM; k++) {
            float4 w = __ldg(Wk1t + k * UO + ub);
            const float4* xq = (const float4*)(xh + k * HR);
            acc8(a1, w, xq[0], xq[1]);
        }
        // fused k<64: Wr1·h1(t-1) [gmem], Wk2f·h1(t-1) [smem], Wr2·h2(t-2) [smem]
#pragma unroll 4
        for (int k = 0; k < UI; k++) {
            float4 w1 = __ldg(Wr1t + k * UO + ub);
            float4 w2 = wbig4[k * UI + us];
            float4 wr = wsmall4[k * UI + us];
            const float4* hq = (const float4*)(h1 + k * HR);
            float4 h1a = hq[0], h1b = hq[1];
            float4 h1sel = *(const float4*)(h1 + k * HR + rs);
            float4 h2q  = *(const float4*)(h2 + k * HR + rs);
            acc8(a1, w1, h1a, h1b);
            acc4(a2, w2, h1sel);
            acc4(a2, wr, h2q);
        }
        // k 64..127: Wr1·h1 [gmem], Wk2f·h1 [smem]
#pragma unroll 4
        for (int k = UI; k < UO; k++) {
            float4 w1 = __ldg(Wr1t + k * UO + ub);
            float4 w2 = wbig4[k * UI + us];
            const float4* hq = (const float4*)(h1 + k * HR);
            float4 h1a = hq[0], h1b = hq[1];
            float4 h1sel = *(const float4*)(h1 + k * HR + rs);
            acc8(a1, w1, h1a, h1b);
            acc4(a2, w2, h1sel);
        }

        barsync(bid);  // old-state reads complete

        gates_write<4>(a1, c1v, h1 + ub * HR);                  // h1(t)
        if (t > 0) gates_write<2>(a2, c2v, h2 + us * HR + rs);  // h2(t-1)
        if (t + 1 < TDIM && ltid < HR * FDIM) {                 // x(t+1)
            int r = ltid >> 3, k = ltid & 7;
            xh[k * HR + r] = x[(size_t)(row0 + r) * TDIM * FDIM + (t + 1) * FDIM + k];
        }
        barsync(bid);  // new state visible
    }

    // epilogue A: h2(127) from h1(127), h2(126)
    {
        float2 a2[4][2];
        init_acc<2>(a2, bb2);
#pragma unroll 4
        for (int k = 0; k < UI; k++) {
            float4 w2 = wbig4[k * UI + us];
            float4 wr = wsmall4[k * UI + us];
            float4 h1sel = *(const float4*)(h1 + k * HR + rs);
            float4 h2q  = *(const float4*)(h2 + k * HR + rs);
            acc4(a2, w2, h1sel);
            acc4(a2, wr, h2q);
        }
#pragma unroll 4
        for (int k = UI; k < UO; k++) {
            float4 w2 = wbig4[k * UI + us];
            float4 h1sel = *(const float4*)(h1 + k * HR + rs);
            acc4(a2, w2, h1sel);
        }
        barsync(bid);
        gates_write<2>(a2, c2v, h2 + us * HR + rs);  // h2(127)
    }

    // ===== transition: xz3 = enc_bn @ Wk3f + b3f; reload smem for phase B ====
    __syncthreads();   // join halves; h2 final everywhere
    float2 x3[4][2];
    {
        float bb3[4];
#pragma unroll
        for (int g = 0; g < 4; g++) bb3[g] = g_b3f[g * UI + us];
        init_acc<2>(x3, bb3);
#pragma unroll 4
        for (int k = 0; k < UI; k++) {
            float4 w = __ldg(Wk3f + k * UI + us);
            float4 hq = *(const float4*)(h2 + k * HR + rs);
            acc4(x3, w, hq);
        }
    }
    {
        float4* d1 = (float4*)wbig;
        const float4* s1 = (const float4*)g_Wk4f;
        for (int i = tid; i < N_WK4F / 4; i += NTHR) d1[i] = s1[i];
        float4* d2 = (float4*)wsmall;
        const float4* s2 = (const float4*)g_Wr3t;
        for (int i = tid; i < N_WR3T / 4; i += NTHR) d2[i] = s2[i];
    }
    __syncthreads();   // phase-B weights staged

    // ========== Phase B: LSTM3(t) fused with LSTM4(t-1) + Dense(t-2) ========
    // Loop-top invariant: h3 = h3(t-1), h4 = h4(t-2).
    const int dr = ltid >> 3, dc = ltid & 7;
    for (int t = 0; t < TDIM; t++) {
        float2 a3[4][2];
#pragma unroll
        for (int g = 0; g < 4; g++) { a3[g][0] = x3[g][0]; a3[g][1] = x3[g][1]; }
        float2 a4[4][4];
        init_acc<4>(a4, bb4);

        // fused k<64: Wr4·h4(t-2) [gmem], Wk4f·h3(t-1) [smem], Wr3·h3(t-1) [smem]
#pragma unroll 4
        for (int k = 0; k < UI; k++) {
            float4 w4 = __ldg(Wr4t + k * UO + ub);
            float4 wk = wbig4[k * UO + ub];
            float4 w3 = wsmall4[k * UI + us];
            const float4* h4q = (const float4*)(h4 + k * HR);
            float4 h4a = h4q[0], h4b = h4q[1];
            const float4* h3q = (const float4*)(h3 + k * HR);
            float4 h3a = h3q[0], h3b = h3q[1];
            float4 h3sel = *(const float4*)(h3 + k * HR + rs);
            acc8(a4, w4, h4a, h4b);
            acc8(a4, wk, h3a, h3b);
            acc4(a3, w3, h3sel);
        }
        // k 64..127: Wr4·h4 only
#pragma unroll 4
        for (int k = UI; k < UO; k++) {
            float4 w4 = __ldg(Wr4t + k * UO + ub);
            const float4* h4q = (const float4*)(h4 + k * HR);
            acc8(a4, w4, h4q[0], h4q[1]);
        }

        // dense head out(t-2) from h4(t-2), overlapped with GEMM reads
        if (t >= 2 && ltid < HR * FDIM) {
            float acc = bds[dc];
#pragma unroll 8
            for (int k = 0; k < UO; k++) acc += h4[k * HR + dr] * wds[k * FDIM + dc];
            out[(size_t)(row0 + dr) * TDIM * FDIM + (t - 2) * FDIM + dc] = acc;
        }

        barsync(bid);  // old-state reads complete

        gates_write<2>(a3, c3v, h3 + us * HR + rs);             // h3(t)
        if (t > 0) gates_write<4>(a4, c4v, h4 + ub * HR);       // h4(t-1)
        barsync(bid);  // new state visible
    }

    // epilogue B: h4(127) from h4(126), h3(127); dense out(126), out(127)
    {
        float2 a4[4][4];
        init_acc<4>(a4, bb4);
#pragma unroll 4
        for (int k = 0; k < UI; k++) {
            float4 w4 = __ldg(Wr4t + k * UO + ub);
            float4 wk = wbig4[k * UO + ub];
            const float4* h4q = (const float4*)(h4 + k * HR);
            const float4* h3q = (const float4*)(h3 + k * HR);
            acc8(a4, w4, h4q[0], h4q[1]);
            acc8(a4, wk, h3q[0], h3q[1]);
        }
#pragma unroll 4
        for (int k = UI; k < UO; k++) {
            float4 w4 = __ldg(Wr4t + k * UO + ub);
            const float4* h4q = (const float4*)(h4 + k * HR);
            acc8(a4, w4, h4q[0], h4q[1]);
        }
        if (ltid < HR * FDIM) {  // out(126) from h4(126)
            float acc = bds[dc];
#pragma unroll 8
            for (int k = 0; k < UO; k++) acc += h4[k * HR + dr] * wds[k * FDIM + dc];
            out[(size_t)(row0 + dr) * TDIM * FDIM + 126 * FDIM + dc] = acc;
        }
        barsync(bid);
        gates_write<4>(a4, c4v, h4 + ub * HR);  // h4(127)
        barsync(bid);
        if (ltid < HR * FDIM) {  // out(127)
            float acc = bds[dc];
#pragma unroll 8
            for (int k = 0; k < UO; k++) acc += h4[k * HR + dr] * wds[k * FDIM + dc];
            out[(size_t)(row0 + dr) * TDIM * FDIM + 127 * FDIM + dc] = acc;
        }
    }
}

// ---------------- launch ------------------------------------------------------
extern "C" void kernel_launch(void* const* d_in, const int* in_sizes, int n_in,
                              void* d_out, int out_size) {
    const float* x   = (const float*)d_in[0];
    const float* Wk1 = (const float*)d_in[1];
    const float* Wr1 = (const float*)d_in[2];
    const float* b1  = (const float*)d_in[3];
    const float* g1  = (const float*)d_in[4];
    const float* be1 = (const float*)d_in[5];
    const float* m1  = (const float*)d_in[6];
    const float* v1  = (const float*)d_in[7];
    const float* Wk2 = (const float*)d_in[8];
    const float* Wr2 = (const float*)d_in[9];
    const float* b2  = (const float*)d_in[10];
    const float* g2  = (const float*)d_in[11];
    const float* be2 = (const float*)d_in[12];
    const float* m2  = (const float*)d_in[13];
    const float* v2  = (const float*)d_in[14];
    const float* Wk3 = (const float*)d_in[15];
    const float* Wr3 = (const float*)d_in[16];
    const float* b3  = (const float*)d_in[17];
    const float* g3  = (const float*)d_in[18];
    const float* be3 = (const float*)d_in[19];
    const float* m3  = (const float*)d_in[20];
    const float* v3  = (const float*)d_in[21];
    const float* Wk4 = (const float*)d_in[22];
    const float* Wr4 = (const float*)d_in[23];
    const float* b4  = (const float*)d_in[24];
    const float* g4  = (const float*)d_in[25];
    const float* be4 = (const float*)d_in[26];
    const float* m4  = (const float*)d_in[27];
    const float* v4  = (const float*)d_in[28];
    const float* Wd  = (const float*)d_in[29];
    const float* bd  = (const float*)d_in[30];

    static bool attr_set = false;
    if (!attr_set) {
        cudaFuncSetAttribute(lstm_ae_kernel,
                             cudaFuncAttributeMaxDynamicSharedMemorySize, SMEM_BYTES);
        attr_set = true;
    }

    prep_all<<<(NTOT + 255) / 256, 256>>>(Wk1, Wr1, Wr2, Wr3, Wr4,
                                          Wk2, b2, Wk3, b3, Wk4, b4, Wd, bd,
                                          g1, be1, m1, v1, g2, be2, m2, v2,
                                          g3, be3, m3, v3, g4, be4, m4, v4);
    lstm_ae_kernel<<<BDIM / BT, NTHR, SMEM_BYTES>>>(x, b1, (float*)d_out);
}

// round 7
// speedup vs baseline: 2.0082x; 1.0679x over previous
#include <cuda_runtime.h>

#define BDIM 2048
#define TDIM 128
#define FDIM 8
#define UO   128
#define UI   64
#define BT   16          // batch rows per CTA (two independent halves of 8)
#define HR   8           // rows per half
#define NTHR 256
#define BN_EPS 1e-3f

// ---------------- device scratch: BN-folded, gate-contiguous weights ---------
// Layout: Wt[(k*U + u)*4 + g]  ->  one float4 load gives all 4 gate weights.
__device__ __align__(16) float g_Wk1t[FDIM * UO * 4];
__device__ __align__(16) float g_Wr1t[UO * UO * 4];
__device__ __align__(16) float g_Wr2t[UI * UI * 4];
__device__ __align__(16) float g_Wr3t[UI * UI * 4];
__device__ __align__(16) float g_Wr4t[UO * UO * 4];
__device__ __align__(16) float g_Wk2f[UO * UI * 4];   // BN1 folded
__device__ __align__(16) float g_Wk3f[UI * UI * 4];   // BN2 folded
__device__ __align__(16) float g_Wk4f[UI * UO * 4];   // BN3 folded
__device__ __align__(16) float g_Wdf[UO * FDIM];      // BN4 folded
__device__ float g_b2f[4 * UI];
__device__ float g_b3f[4 * UI];
__device__ float g_b4f[4 * UO];
__device__ float g_bdf[FDIM];

// ---------------- dynamic smem layout (floats) --------------------------------
#define SM_WBIG   0                            // 32768: Wk2f (A) / Wk4f (B)
#define SM_WSMALL 32768                        // 16384: Wr2t (A) / Wr3t (B)
#define SM_H1     (SM_WSMALL + 16384)          // 2048
#define SM_H2     (SM_H1 + 2048)               // 1024
#define SM_H3     (SM_H2 + 1024)               // 1024
#define SM_H4     (SM_H3 + 1024)               // 2048
#define SM_XS     (SM_H4 + 2048)               // 128
#define SM_WDS    (SM_XS + 128)                // 1024
#define SM_BDS    (SM_WDS + 1024)              // 8
#define SM_TOTAL  (SM_BDS + 8)                 // 56456 floats = 225824 B
#define SMEM_BYTES (SM_TOTAL * 4)

// ---------------- helpers ----------------------------------------------------
__device__ __forceinline__ float2 ffma2f(float2 a, float2 b, float2 c) {
    union U { float2 f; unsigned long long u; };
    U A, B, C, D;
    A.f = a; B.f = b; C.f = c;
    asm("fma.rn.f32x2 %0, %1, %2, %3;" : "=l"(D.u) : "l"(A.u), "l"(B.u), "l"(C.u));
    return D.f;
}

__device__ __forceinline__ void barsync(int id) {
    asm volatile("bar.sync %0, 128;" :: "r"(id) : "memory");
}

__device__ __forceinline__ float tanh_fast(float x) {
    float y;
    asm("tanh.approx.f32 %0, %1;" : "=f"(y) : "f"(x));
    return y;
}

// sigmoid(x) = 0.5*tanh(0.5x)+0.5 : 1 MUFU instead of 2
__device__ __forceinline__ float sigm(float x) {
    return fmaf(0.5f, tanh_fast(0.5f * x), 0.5f);
}

__device__ __forceinline__ float seluf(float x) {
    const float l = 1.0507009873554805f;
    const float a = 1.6732632423543772f;
    return x > 0.0f ? l * x : l * a * (__expf(x) - 1.0f);
}

__device__ __forceinline__ void gate_update(float zi, float zf, float zg, float zo,
                                            float& c, float& h) {
    float i = sigm(zi), f = sigm(zf), g = seluf(zg), o = sigm(zo);
    c = f * c + i * g;
    h = o * seluf(c);
}

// acc[4][4] covers 8 rows (2 quads); 16 FFMA2
__device__ __forceinline__ void acc8(float2 (&acc)[4][4], float4 w, float4 h0, float4 h1) {
    float ws[4] = {w.x, w.y, w.z, w.w};
#pragma unroll
    for (int g = 0; g < 4; g++) {
        float2 W = make_float2(ws[g], ws[g]);
        acc[g][0] = ffma2f(make_float2(h0.x, h0.y), W, acc[g][0]);
        acc[g][1] = ffma2f(make_float2(h0.z, h0.w), W, acc[g][1]);
        acc[g][2] = ffma2f(make_float2(h1.x, h1.y), W, acc[g][2]);
        acc[g][3] = ffma2f(make_float2(h1.z, h1.w), W, acc[g][3]);
    }
}

// acc[4][2] covers 4 rows (1 quad); 8 FFMA2
__device__ __forceinline__ void acc4(float2 (&acc)[4][2], float4 w, float4 h) {
    float ws[4] = {w.x, w.y, w.z, w.w};
#pragma unroll
    for (int g = 0; g < 4; g++) {
        float2 W = make_float2(ws[g], ws[g]);
        acc[g][0] = ffma2f(make_float2(h.x, h.y), W, acc[g][0]);
        acc[g][1] = ffma2f(make_float2(h.z, h.w), W, acc[g][1]);
    }
}

template <int NP>
__device__ __forceinline__ void init_acc(float2 (&acc)[4][NP], const float b[4]) {
#pragma unroll
    for (int g = 0; g < 4; g++)
#pragma unroll
        for (int p = 0; p < NP; p++) acc[g][p] = make_float2(b[g], b[g]);
}

template <int NP>
__device__ __forceinline__ void gates_write(float2 (&acc)[4][NP], float* cvec, float* hrow) {
#pragma unroll
    for (int p = 0; p < NP; p++) {
        {
            float c = cvec[2 * p], h;
            gate_update(acc[0][p].x, acc[1][p].x, acc[2][p].x, acc[3][p].x, c, h);
            cvec[2 * p] = c; hrow[2 * p] = h;
        }
        {
            float c = cvec[2 * p + 1], h;
            gate_update(acc[0][p].y, acc[1][p].y, acc[2][p].y, acc[3][p].y, c, h);
            cvec[2 * p + 1] = c; hrow[2 * p + 1] = h;
        }
    }
}

// ---------------- single merged prep kernel -----------------------------------
#define N_WK1T  (FDIM * UO * 4)
#define N_WR1T  (UO * UO * 4)
#define N_WR2T  (UI * UI * 4)
#define N_WR3T  (UI * UI * 4)
#define N_WR4T  (UO * UO * 4)
#define N_WK2F  (UO * UI * 4)
#define N_WK3F  (UI * UI * 4)
#define N_WK4F  (UI * UO * 4)
#define N_WDF   (UO * FDIM)
#define O1 N_WK1T
#define O2 (O1 + N_WR1T)
#define O3 (O2 + N_WR2T)
#define O4 (O3 + N_WR3T)
#define O5 (O4 + N_WR4T)
#define O6 (O5 + N_WK2F)
#define O7 (O6 + N_WK3F)
#define O8 (O7 + N_WK4F)
#define O9 (O8 + N_WDF)
#define OA (O9 + 4 * UI)
#define OB (OA + 4 * UI)
#define OC (OB + 4 * UO)
#define OD (OC + FDIM)
#define NTOT OD

__device__ __forceinline__ float bn_s(const float* g, const float* v, int k) {
    return g[k] * rsqrtf(v[k] + BN_EPS);
}
__device__ __forceinline__ float bn_sh(const float* g, const float* be, const float* m,
                                       const float* v, int k) {
    float s = g[k] * rsqrtf(v[k] + BN_EPS);
    return be[k] - m[k] * s;
}

__global__ void prep_all(const float* __restrict__ Wk1, const float* __restrict__ Wr1,
                         const float* __restrict__ Wr2, const float* __restrict__ Wr3,
                         const float* __restrict__ Wr4,
                         const float* __restrict__ Wk2, const float* __restrict__ b2,
                         const float* __restrict__ Wk3, const float* __restrict__ b3,
                         const float* __restrict__ Wk4, const float* __restrict__ b4,
                         const float* __restrict__ Wd,  const float* __restrict__ bd,
                         const float* __restrict__ g1, const float* __restrict__ be1,
                         const float* __restrict__ m1, const float* __restrict__ v1,
                         const float* __restrict__ g2, const float* __restrict__ be2,
                         const float* __restrict__ m2, const float* __restrict__ v2,
                         const float* __restrict__ g3, const float* __restrict__ be3,
                         const float* __restrict__ m3, const float* __restrict__ v3,
                         const float* __restrict__ g4, const float* __restrict__ be4,
                         const float* __restrict__ m4, const float* __restrict__ v4) {
    int e = blockIdx.x * blockDim.x + threadIdx.x;
    if (e >= NTOT) return;
    if (e < O1) {
        int g = e & 3, u = (e >> 2) & (UO - 1), k = e >> 9;
        g_Wk1t[e] = Wk1[k * 4 * UO + g * UO + u];
    } else if (e < O2) {
        int i = e - O1;
        int g = i & 3, u = (i >> 2) & (UO - 1), k = i >> 9;
        g_Wr1t[i] = Wr1[k * 4 * UO + g * UO + u];
    } else if (e < O3) {
        int i = e - O2;
        int g = i & 3, u = (i >> 2) & (UI - 1), k = i >> 8;
        g_Wr2t[i] = Wr2[k * 4 * UI + g * UI + u];
    } else if (e < O4) {
        int i = e - O3;
        int g = i & 3, u = (i >> 2) & (UI - 1), k = i >> 8;
        g_Wr3t[i] = Wr3[k * 4 * UI + g * UI + u];
    } else if (e < O5) {
        int i = e - O4;
        int g = i & 3, u = (i >> 2) & (UO - 1), k = i >> 9;
        g_Wr4t[i] = Wr4[k * 4 * UO + g * UO + u];
    } else if (e < O6) {
        int i = e - O5;
        int g = i & 3, u = (i >> 2) & (UI - 1), k = i >> 8;
        g_Wk2f[i] = bn_s(g1, v1, k) * Wk2[k * 4 * UI + g * UI + u];
    } else if (e < O7) {
        int i = e - O6;
        int g = i & 3, u = (i >> 2) & (UI - 1), k = i >> 8;
        g_Wk3f[i] = bn_s(g2, v2, k) * Wk3[k * 4 * UI + g * UI + u];
    } else if (e < O8) {
        int i = e - O7;
        int g = i & 3, u = (i >> 2) & (UO - 1), k = i >> 9;
        g_Wk4f[i] = bn_s(g3, v3, k) * Wk4[k * 4 * UO + g * UO + u];
    } else if (e < O9) {
        int i = e - O8;
        int k = i >> 3;
        g_Wdf[i] = bn_s(g4, v4, k) * Wd[i];
    } else if (e < OA) {
        int c = e - O9;
        float acc = b2[c];
        for (int k = 0; k < UO; k++) acc += bn_sh(g1, be1, m1, v1, k) * Wk2[k * 4 * UI + c];
        g_b2f[c] = acc;
    } else if (e < OB) {
        int c = e - OA;
        float acc = b3[c];
        for (int k = 0; k < UI; k++) acc += bn_sh(g2, be2, m2, v2, k) * Wk3[k * 4 * UI + c];
        g_b3f[c] = acc;
    } else if (e < OC) {
        int c = e - OB;
        float acc = b4[c];
        for (int k = 0; k < UI; k++) acc += bn_sh(g3, be3, m3, v3, k) * Wk4[k * 4 * UO + c];
        g_b4f[c] = acc;
    } else {
        int c = e - OC;
        float acc = bd[c];
        for (int k = 0; k < UO; k++) acc += bn_sh(g4, be4, m4, v4, k) * Wd[k * FDIM + c];
        g_bdf[c] = acc;
    }
}

// ---------------- main: deep-staged LDG pipeline + smem weights ---------------
__global__ __launch_bounds__(NTHR, 1)
void lstm_ae_kernel(const float* __restrict__ x,
                    const float* __restrict__ b1,
                    float* __restrict__ out) {
    extern __shared__ __align__(16) float sm[];
    float* wbig   = sm + SM_WBIG;     // Wk2f (phase A) / Wk4f (phase B)
    float* wsmall = sm + SM_WSMALL;   // Wr2t (phase A) / Wr3t (phase B)
    float* wds    = sm + SM_WDS;
    float* bds    = sm + SM_BDS;

    const int tid  = threadIdx.x;
    const int half = tid >> 7;
    const int ltid = tid & 127;
    const int bid  = 1 + half;
    const int row0 = blockIdx.x * BT + half * HR;

    float* h1 = sm + SM_H1 + half * (UO * HR);
    float* h2 = sm + SM_H2 + half * (UI * HR);
    float* h3 = sm + SM_H3 + half * (UI * HR);
    float* h4 = sm + SM_H4 + half * (UO * HR);
    float* xh = sm + SM_XS + half * (FDIM * HR);

    const int ub = ltid;                 // big GEMMs: u-quad, all 8 rows
    const int us = ltid & 63;            // small GEMMs: u-quad
    const int rs = (ltid >> 6) * 4;      // small GEMMs: row-quad offset (0 or 4)
    const bool hiq = (ltid >= 64);       // warp-uniform: which quad rs selects

    // zero state, load dense weights, stage phase-A smem weights
    for (int i = tid; i < UO * HR * 2; i += NTHR) { sm[SM_H1 + i] = 0.f; sm[SM_H4 + i] = 0.f; }
    for (int i = tid; i < UI * HR * 2; i += NTHR) { sm[SM_H2 + i] = 0.f; sm[SM_H3 + i] = 0.f; }
    for (int i = tid; i < UO * FDIM; i += NTHR) wds[i] = g_Wdf[i];
    if (tid < FDIM) bds[tid] = g_bdf[tid];
    if (ltid < HR * FDIM) {
        int r = ltid >> 3, k = ltid & 7;
        xh[k * HR + r] = x[(size_t)(row0 + r) * TDIM * FDIM + k];
    }
    {
        float4* d1 = (float4*)wbig;
        const float4* s1 = (const float4*)g_Wk2f;
        for (int i = tid; i < N_WK2F / 4; i += NTHR) d1[i] = s1[i];
        float4* d2 = (float4*)wsmall;
        const float4* s2 = (const float4*)g_Wr2t;
        for (int i = tid; i < N_WR2T / 4; i += NTHR) d2[i] = s2[i];
    }

    float bb1[4], bb2[4], bb4[4];
#pragma unroll
    for (int g = 0; g < 4; g++) {
        bb1[g] = b1[g * UO + ub];
        bb2[g] = g_b2f[g * UI + us];
        bb4[g] = g_b4f[g * UO + ub];
    }

    float c1v[8], c4v[8], c2v[4], c3v[4];
#pragma unroll
    for (int i = 0; i < 8; i++) { c1v[i] = 0.f; c4v[i] = 0.f; }
#pragma unroll
    for (int i = 0; i < 4; i++) { c2v[i] = 0.f; c3v[i] = 0.f; }

    const float4* Wk1t = (const float4*)g_Wk1t;
    const float4* Wr1t = (const float4*)g_Wr1t;
    const float4* Wr4t = (const float4*)g_Wr4t;
    const float4* Wk3f = (const float4*)g_Wk3f;
    const float4* wbig4   = (const float4*)wbig;
    const float4* wsmall4 = (const float4*)wsmall;

    __syncthreads();

    // ========== Phase A: LSTM1(t) fused with LSTM2(t-1), pipelined ==========
    // Loop-top invariant: h1 = h1(t-1), h2 = h2(t-2), xh = x(t).
    for (int t = 0; t < TDIM; t++) {
        float2 a1[4][4];
        init_acc<4>(a1, bb1);
        float2 a2[4][2];
        init_acc<2>(a2, bb2);

        // z1 input part: x(t) @ Wk1 — stage all 8 LDGs up front
        {
            float4 wb[FDIM];
#pragma unroll
            for (int k = 0; k < FDIM; k++) wb[k] = __ldg(Wk1t + k * UO + ub);
#pragma unroll
            for (int k = 0; k < FDIM; k++) {
                const float4* xq = (const float4*)(xh + k * HR);
                acc8(a1, wb[k], xq[0], xq[1]);
            }
        }
        // fused k<64: Wr1·h1(t-1) [gmem, 8-deep staged], Wk2f·h1 [smem], Wr2·h2 [smem]
        for (int k0 = 0; k0 < UI; k0 += 8) {
            float4 w1b[8];
#pragma unroll
            for (int j = 0; j < 8; j++) w1b[j] = __ldg(Wr1t + (k0 + j) * UO + ub);
#pragma unroll
            for (int j = 0; j < 8; j++) {
                int k = k0 + j;
                float4 w2 = wbig4[k * UI + us];
                float4 wr = wsmall4[k * UI + us];
                const float4* hq = (const float4*)(h1 + k * HR);
                float4 h1a = hq[0], h1b = hq[1];
                float4 h1sel = hiq ? h1b : h1a;     // register select, no LDS
                float4 h2q = *(const float4*)(h2 + k * HR + rs);
                acc8(a1, w1b[j], h1a, h1b);
                acc4(a2, w2, h1sel);
                acc4(a2, wr, h2q);
            }
        }
        // k 64..127: Wr1·h1 [gmem, staged], Wk2f·h1 [smem]
        for (int k0 = UI; k0 < UO; k0 += 8) {
            float4 w1b[8];
#pragma unroll
            for (int j = 0; j < 8; j++) w1b[j] = __ldg(Wr1t + (k0 + j) * UO + ub);
#pragma unroll
            for (int j = 0; j < 8; j++) {
                int k = k0 + j;
                float4 w2 = wbig4[k * UI + us];
                const float4* hq = (const float4*)(h1 + k * HR);
                float4 h1a = hq[0], h1b = hq[1];
                float4 h1sel = hiq ? h1b : h1a;
                acc8(a1, w1b[j], h1a, h1b);
                acc4(a2, w2, h1sel);
            }
        }

        barsync(bid);  // old-state reads complete

        gates_write<4>(a1, c1v, h1 + ub * HR);                  // h1(t)
        if (t > 0) gates_write<2>(a2, c2v, h2 + us * HR + rs);  // h2(t-1)
        if (t + 1 < TDIM && ltid < HR * FDIM) {                 // x(t+1)
            int r = ltid >> 3, k = ltid & 7;
            xh[k * HR + r] = x[(size_t)(row0 + r) * TDIM * FDIM + (t + 1) * FDIM + k];
        }
        barsync(bid);  // new state visible
    }

    // epilogue A: h2(127) from h1(127), h2(126)
    {
        float2 a2[4][2];
        init_acc<2>(a2, bb2);
#pragma unroll 4
        for (int k = 0; k < UI; k++) {
            float4 w2 = wbig4[k * UI + us];
            float4 wr = wsmall4[k * UI + us];
            float4 h1sel = *(const float4*)(h1 + k * HR + rs);
            float4 h2q  = *(const float4*)(h2 + k * HR + rs);
            acc4(a2, w2, h1sel);
            acc4(a2, wr, h2q);
        }
#pragma unroll 4
        for (int k = UI; k < UO; k++) {
            float4 w2 = wbig4[k * UI + us];
            float4 h1sel = *(const float4*)(h1 + k * HR + rs);
            acc4(a2, w2, h1sel);
        }
        barsync(bid);
        gates_write<2>(a2, c2v, h2 + us * HR + rs);  // h2(127)
    }

    // ===== transition: xz3 = enc_bn @ Wk3f + b3f; reload smem for phase B ====
    __syncthreads();   // join halves; h2 final everywhere
    float2 x3[4][2];
    {
        float bb3[4];
#pragma unroll
        for (int g = 0; g < 4; g++) bb3[g] = g_b3f[g * UI + us];
        init_acc<2>(x3, bb3);
#pragma unroll 4
        for (int k = 0; k < UI; k++) {
            float4 w = __ldg(Wk3f + k * UI + us);
            float4 hq = *(const float4*)(h2 + k * HR + rs);
            acc4(x3, w, hq);
        }
    }
    {
        float4* d1 = (float4*)wbig;
        const float4* s1 = (const float4*)g_Wk4f;
        for (int i = tid; i < N_WK4F / 4; i += NTHR) d1[i] = s1[i];
        float4* d2 = (float4*)wsmall;
        const float4* s2 = (const float4*)g_Wr3t;
        for (int i = tid; i < N_WR3T / 4; i += NTHR) d2[i] = s2[i];
    }
    __syncthreads();   // phase-B weights staged

    // ========== Phase B: LSTM3(t) fused with LSTM4(t-1) + Dense(t-2) ========
    // Loop-top invariant: h3 = h3(t-1), h4 = h4(t-2).
    const int dr = ltid >> 3, dc = ltid & 7;
    for (int t = 0; t < TDIM; t++) {
        float2 a3[4][2];
#pragma unroll
        for (int g = 0; g < 4; g++) { a3[g][0] = x3[g][0]; a3[g][1] = x3[g][1]; }
        float2 a4[4][4];
        init_acc<4>(a4, bb4);

        // fused k<64: Wr4·h4(t-2) [gmem, staged], Wk4f·h3(t-1) [smem], Wr3·h3 [smem]
        for (int k0 = 0; k0 < UI; k0 += 8) {
            float4 w4b[8];
#pragma unroll
            for (int j = 0; j < 8; j++) w4b[j] = __ldg(Wr4t + (k0 + j) * UO + ub);
#pragma unroll
            for (int j = 0; j < 8; j++) {
                int k = k0 + j;
                float4 wk = wbig4[k * UO + ub];
                float4 w3 = wsmall4[k * UI + us];
                const float4* h4q = (const float4*)(h4 + k * HR);
                float4 h4a = h4q[0], h4b = h4q[1];
                const float4* h3q = (const float4*)(h3 + k * HR);
                float4 h3a = h3q[0], h3b = h3q[1];
                float4 h3sel = hiq ? h3b : h3a;     // register select, no LDS
                acc8(a4, w4b[j], h4a, h4b);
                acc8(a4, wk, h3a, h3b);
                acc4(a3, w3, h3sel);
            }
        }
        // k 64..127: Wr4·h4 only [gmem, staged]
        for (int k0 = UI; k0 < UO; k0 += 8) {
            float4 w4b[8];
#pragma unroll
            for (int j = 0; j < 8; j++) w4b[j] = __ldg(Wr4t + (k0 + j) * UO + ub);
#pragma unroll
            for (int j = 0; j < 8; j++) {
                const float4* h4q = (const float4*)(h4 + (k0 + j) * HR);
                acc8(a4, w4b[j], h4q[0], h4q[1]);
            }
        }

        // dense head out(t-2) from h4(t-2), overlapped with GEMM reads
        if (t >= 2 && ltid < HR * FDIM) {
            float acc = bds[dc];
#pragma unroll 8
            for (int k = 0; k < UO; k++) acc += h4[k * HR + dr] * wds[k * FDIM + dc];
            out[(size_t)(row0 + dr) * TDIM * FDIM + (t - 2) * FDIM + dc] = acc;
        }

        barsync(bid);  // old-state reads complete

        gates_write<2>(a3, c3v, h3 + us * HR + rs);             // h3(t)
        if (t > 0) gates_write<4>(a4, c4v, h4 + ub * HR);       // h4(t-1)
        barsync(bid);  // new state visible
    }

    // epilogue B: h4(127) from h4(126), h3(127); dense out(126), out(127)
    {
        float2 a4[4][4];
        init_acc<4>(a4, bb4);
#pragma unroll 4
        for (int k = 0; k < UI; k++) {
            float4 w4 = __ldg(Wr4t + k * UO + ub);
            float4 wk = wbig4[k * UO + ub];
            const float4* h4q = (const float4*)(h4 + k * HR);
            const float4* h3q = (const float4*)(h3 + k * HR);
            acc8(a4, w4, h4q[0], h4q[1]);
            acc8(a4, wk, h3q[0], h3q[1]);
        }
#pragma unroll 4
        for (int k = UI; k < UO; k++) {
            float4 w4 = __ldg(Wr4t + k * UO + ub);
            const float4* h4q = (const float4*)(h4 + k * HR);
            acc8(a4, w4, h4q[0], h4q[1]);
        }
        if (ltid < HR * FDIM) {  // out(126) from h4(126)
            float acc = bds[dc];
#pragma unroll 8
            for (int k = 0; k < UO; k++) acc += h4[k * HR + dr] * wds[k * FDIM + dc];
            out[(size_t)(row0 + dr) * TDIM * FDIM + 126 * FDIM + dc] = acc;
        }
        barsync(bid);
        gates_write<4>(a4, c4v, h4 + ub * HR);  // h4(127)
        barsync(bid);
        if (ltid < HR * FDIM) {  // out(127)
            float acc = bds[dc];
#pragma unroll 8
            for (int k = 0; k < UO; k++) acc += h4[k * HR + dr] * wds[k * FDIM + dc];
            out[(size_t)(row0 + dr) * TDIM * FDIM + 127 * FDIM + dc] = acc;
        }
    }
}

// ---------------- launch ------------------------------------------------------
extern "C" void kernel_launch(void* const* d_in, const int* in_sizes, int n_in,
                              void* d_out, int out_size) {
    const float* x   = (const float*)d_in[0];
    const float* Wk1 = (const float*)d_in[1];
    const float* Wr1 = (const float*)d_in[2];
    const float* b1  = (const float*)d_in[3];
    const float* g1  = (const float*)d_in[4];
    const float* be1 = (const float*)d_in[5];
    const float* m1  = (const float*)d_in[6];
    const float* v1  = (const float*)d_in[7];
    const float* Wk2 = (const float*)d_in[8];
    const float* Wr2 = (const float*)d_in[9];
    const float* b2  = (const float*)d_in[10];
    const float* g2  = (const float*)d_in[11];
    const float* be2 = (const float*)d_in[12];
    const float* m2  = (const float*)d_in[13];
    const float* v2  = (const float*)d_in[14];
    const float* Wk3 = (const float*)d_in[15];
    const float* Wr3 = (const float*)d_in[16];
    const float* b3  = (const float*)d_in[17];
    const float* g3  = (const float*)d_in[18];
    const float* be3 = (const float*)d_in[19];
    const float* m3  = (const float*)d_in[20];
    const float* v3  = (const float*)d_in[21];
    const float* Wk4 = (const float*)d_in[22];
    const float* Wr4 = (const float*)d_in[23];
    const float* b4  = (const float*)d_in[24];
    const float* g4  = (const float*)d_in[25];
    const float* be4 = (const float*)d_in[26];
    const float* m4  = (const float*)d_in[27];
    const float* v4  = (const float*)d_in[28];
    const float* Wd  = (const float*)d_in[29];
    const float* bd  = (const float*)d_in[30];

    static bool attr_set = false;
    if (!attr_set) {
        cudaFuncSetAttribute(lstm_ae_kernel,
                             cudaFuncAttributeMaxDynamicSharedMemorySize, SMEM_BYTES);
        attr_set = true;
    }

    prep_all<<<(NTOT + 255) / 256, 256>>>(Wk1, Wr1, Wr2, Wr3, Wr4,
                                          Wk2, b2, Wk3, b3, Wk4, b4, Wd, bd,
                                          g1, be1, m1, v1, g2, be2, m2, v2,
                                          g3, be3, m3, v3, g4, be4, m4, v4);
    lstm_ae_kernel<<<BDIM / BT, NTHR, SMEM_BYTES>>>(x, b1, (float*)d_out);
}

// round 8
// speedup vs baseline: 2.2455x; 1.1181x over previous
#include <cuda_runtime.h>

#define BDIM 2048
#define TDIM 128
#define FDIM 8
#define UO   128
#define UI   64
#define BT   16          // batch rows per CTA (two independent halves of 8)
#define HR   8           // rows per half
#define NTHR 256
#define BN_EPS 1e-3f

// ---------------- device scratch: BN-folded, gate-contiguous weights ---------
// Layout: Wt[(k*U + u)*4 + g]  ->  one float4 load gives all 4 gate weights.
__device__ __align__(16) float g_Wk1t[FDIM * UO * 4];
__device__ __align__(16) float g_Wr1t[UO * UO * 4];
__device__ __align__(16) float g_Wr2t[UI * UI * 4];
__device__ __align__(16) float g_Wr3t[UI * UI * 4];
__device__ __align__(16) float g_Wr4t[UO * UO * 4];
__device__ __align__(16) float g_Wk2f[UO * UI * 4];   // BN1 folded
__device__ __align__(16) float g_Wk3f[UI * UI * 4];   // BN2 folded
__device__ __align__(16) float g_Wk4f[UI * UO * 4];   // BN3 folded
__device__ __align__(16) float g_Wdf[UO * FDIM];      // BN4 folded
__device__ float g_b2f[4 * UI];
__device__ float g_b3f[4 * UI];
__device__ float g_b4f[4 * UO];
__device__ float g_bdf[FDIM];

// ---------------- dynamic smem layout (floats) --------------------------------
#define SM_WBIG   0                            // 32768: Wk2f (A) / Wk4f (B)
#define SM_WSMALL 32768                        // 16384: Wr2t (A) / Wr3t (B)
#define SM_H1     (SM_WSMALL + 16384)          // 2048
#define SM_H2     (SM_H1 + 2048)               // 1024
#define SM_H3     (SM_H2 + 1024)               // 1024
#define SM_H4     (SM_H3 + 1024)               // 2048
#define SM_XS     (SM_H4 + 2048)               // 128
#define SM_WDS    (SM_XS + 128)                // 1024
#define SM_BDS    (SM_WDS + 1024)              // 8
#define SM_TOTAL  (SM_BDS + 8)                 // 56456 floats = 225824 B
#define SMEM_BYTES (SM_TOTAL * 4)

// ---------------- helpers ----------------------------------------------------
__device__ __forceinline__ float2 ffma2f(float2 a, float2 b, float2 c) {
    union U { float2 f; unsigned long long u; };
    U A, B, C, D;
    A.f = a; B.f = b; C.f = c;
    asm("fma.rn.f32x2 %0, %1, %2, %3;" : "=l"(D.u) : "l"(A.u), "l"(B.u), "l"(C.u));
    return D.f;
}

__device__ __forceinline__ void barsync(int id) {
    asm volatile("bar.sync %0, 128;" :: "r"(id) : "memory");
}

__device__ __forceinline__ float tanh_fast(float x) {
    float y;
    asm("tanh.approx.f32 %0, %1;" : "=f"(y) : "f"(x));
    return y;
}

// sigmoid(x) = 0.5*tanh(0.5x)+0.5 : 1 MUFU instead of 2
__device__ __forceinline__ float sigm(float x) {
    return fmaf(0.5f, tanh_fast(0.5f * x), 0.5f);
}

__device__ __forceinline__ float seluf(float x) {
    const float l = 1.0507009873554805f;
    const float a = 1.6732632423543772f;
    return x > 0.0f ? l * x : l * a * (__expf(x) - 1.0f);
}

__device__ __forceinline__ void gate_update(float zi, float zf, float zg, float zo,
                                            float& c, float& h) {
    float i = sigm(zi), f = sigm(zf), g = seluf(zg), o = sigm(zo);
    c = f * c + i * g;
    h = o * seluf(c);
}

// acc[4][4] covers 8 rows (2 quads); 16 FFMA2
__device__ __forceinline__ void acc8(float2 (&acc)[4][4], float4 w, float4 h0, float4 h1) {
    float ws[4] = {w.x, w.y, w.z, w.w};
#pragma unroll
    for (int g = 0; g < 4; g++) {
        float2 W = make_float2(ws[g], ws[g]);
        acc[g][0] = ffma2f(make_float2(h0.x, h0.y), W, acc[g][0]);
        acc[g][1] = ffma2f(make_float2(h0.z, h0.w), W, acc[g][1]);
        acc[g][2] = ffma2f(make_float2(h1.x, h1.y), W, acc[g][2]);
        acc[g][3] = ffma2f(make_float2(h1.z, h1.w), W, acc[g][3]);
    }
}

// acc[4][2] covers 4 rows (1 quad); 8 FFMA2
__device__ __forceinline__ void acc4(float2 (&acc)[4][2], float4 w, float4 h) {
    float ws[4] = {w.x, w.y, w.z, w.w};
#pragma unroll
    for (int g = 0; g < 4; g++) {
        float2 W = make_float2(ws[g], ws[g]);
        acc[g][0] = ffma2f(make_float2(h.x, h.y), W, acc[g][0]);
        acc[g][1] = ffma2f(make_float2(h.z, h.w), W, acc[g][1]);
    }
}

template <int NP>
__device__ __forceinline__ void init_acc(float2 (&acc)[4][NP], const float b[4]) {
#pragma unroll
    for (int g = 0; g < 4; g++)
#pragma unroll
        for (int p = 0; p < NP; p++) acc[g][p] = make_float2(b[g], b[g]);
}

template <int NP>
__device__ __forceinline__ void gates_write(float2 (&acc)[4][NP], float* cvec, float* hrow) {
#pragma unroll
    for (int p = 0; p < NP; p++) {
        {
            float c = cvec[2 * p], h;
            gate_update(acc[0][p].x, acc[1][p].x, acc[2][p].x, acc[3][p].x, c, h);
            cvec[2 * p] = c; hrow[2 * p] = h;
        }
        {
            float c = cvec[2 * p + 1], h;
            gate_update(acc[0][p].y, acc[1][p].y, acc[2][p].y, acc[3][p].y, c, h);
            cvec[2 * p + 1] = c; hrow[2 * p + 1] = h;
        }
    }
}

// ---------------- single merged prep kernel -----------------------------------
#define N_WK1T  (FDIM * UO * 4)
#define N_WR1T  (UO * UO * 4)
#define N_WR2T  (UI * UI * 4)
#define N_WR3T  (UI * UI * 4)
#define N_WR4T  (UO * UO * 4)
#define N_WK2F  (UO * UI * 4)
#define N_WK3F  (UI * UI * 4)
#define N_WK4F  (UI * UO * 4)
#define N_WDF   (UO * FDIM)
#define O1 N_WK1T
#define O2 (O1 + N_WR1T)
#define O3 (O2 + N_WR2T)
#define O4 (O3 + N_WR3T)
#define O5 (O4 + N_WR4T)
#define O6 (O5 + N_WK2F)
#define O7 (O6 + N_WK3F)
#define O8 (O7 + N_WK4F)
#define O9 (O8 + N_WDF)
#define OA (O9 + 4 * UI)
#define OB (OA + 4 * UI)
#define OC (OB + 4 * UO)
#define OD (OC + FDIM)
#define NTOT OD

__device__ __forceinline__ float bn_s(const float* g, const float* v, int k) {
    return g[k] * rsqrtf(v[k] + BN_EPS);
}
__device__ __forceinline__ float bn_sh(const float* g, const float* be, const float* m,
                                       const float* v, int k) {
    float s = g[k] * rsqrtf(v[k] + BN_EPS);
    return be[k] - m[k] * s;
}

__global__ void prep_all(const float* __restrict__ Wk1, const float* __restrict__ Wr1,
                         const float* __restrict__ Wr2, const float* __restrict__ Wr3,
                         const float* __restrict__ Wr4,
                         const float* __restrict__ Wk2, const float* __restrict__ b2,
                         const float* __restrict__ Wk3, const float* __restrict__ b3,
                         const float* __restrict__ Wk4, const float* __restrict__ b4,
                         const float* __restrict__ Wd,  const float* __restrict__ bd,
                         const float* __restrict__ g1, const float* __restrict__ be1,
                         const float* __restrict__ m1, const float* __restrict__ v1,
                         const float* __restrict__ g2, const float* __restrict__ be2,
                         const float* __restrict__ m2, const float* __restrict__ v2,
                         const float* __restrict__ g3, const float* __restrict__ be3,
                         const float* __restrict__ m3, const float* __restrict__ v3,
                         const float* __restrict__ g4, const float* __restrict__ be4,
                         const float* __restrict__ m4, const float* __restrict__ v4) {
    int e = blockIdx.x * blockDim.x + threadIdx.x;
    if (e >= NTOT) return;
    if (e < O1) {
        int g = e & 3, u = (e >> 2) & (UO - 1), k = e >> 9;
        g_Wk1t[e] = Wk1[k * 4 * UO + g * UO + u];
    } else if (e < O2) {
        int i = e - O1;
        int g = i & 3, u = (i >> 2) & (UO - 1), k = i >> 9;
        g_Wr1t[i] = Wr1[k * 4 * UO + g * UO + u];
    } else if (e < O3) {
        int i = e - O2;
        int g = i & 3, u = (i >> 2) & (UI - 1), k = i >> 8;
        g_Wr2t[i] = Wr2[k * 4 * UI + g * UI + u];
    } else if (e < O4) {
        int i = e - O3;
        int g = i & 3, u = (i >> 2) & (UI - 1), k = i >> 8;
        g_Wr3t[i] = Wr3[k * 4 * UI + g * UI + u];
    } else if (e < O5) {
        int i = e - O4;
        int g = i & 3, u = (i >> 2) & (UO - 1), k = i >> 9;
        g_Wr4t[i] = Wr4[k * 4 * UO + g * UO + u];
    } else if (e < O6) {
        int i = e - O5;
        int g = i & 3, u = (i >> 2) & (UI - 1), k = i >> 8;
        g_Wk2f[i] = bn_s(g1, v1, k) * Wk2[k * 4 * UI + g * UI + u];
    } else if (e < O7) {
        int i = e - O6;
        int g = i & 3, u = (i >> 2) & (UI - 1), k = i >> 8;
        g_Wk3f[i] = bn_s(g2, v2, k) * Wk3[k * 4 * UI + g * UI + u];
    } else if (e < O8) {
        int i = e - O7;
        int g = i & 3, u = (i >> 2) & (UO - 1), k = i >> 9;
        g_Wk4f[i] = bn_s(g3, v3, k) * Wk4[k * 4 * UO + g * UO + u];
    } else if (e < O9) {
        int i = e - O8;
        int k = i >> 3;
        g_Wdf[i] = bn_s(g4, v4, k) * Wd[i];
    } else if (e < OA) {
        int c = e - O9;
        float acc = b2[c];
        for (int k = 0; k < UO; k++) acc += bn_sh(g1, be1, m1, v1, k) * Wk2[k * 4 * UI + c];
        g_b2f[c] = acc;
    } else if (e < OB) {
        int c = e - OA;
        float acc = b3[c];
        for (int k = 0; k < UI; k++) acc += bn_sh(g2, be2, m2, v2, k) * Wk3[k * 4 * UI + c];
        g_b3f[c] = acc;
    } else if (e < OC) {
        int c = e - OB;
        float acc = b4[c];
        for (int k = 0; k < UI; k++) acc += bn_sh(g3, be3, m3, v3, k) * Wk4[k * 4 * UO + c];
        g_b4f[c] = acc;
    } else {
        int c = e - OC;
        float acc = bd[c];
        for (int k = 0; k < UO; k++) acc += bn_sh(g4, be4, m4, v4, k) * Wd[k * FDIM + c];
        g_bdf[c] = acc;
    }
}

// 8-deep weight-block load into register buffer
#define LD8(BUF, BASE, K0)                                                  \
    do {                                                                    \
        _Pragma("unroll")                                                   \
        for (int j_ = 0; j_ < 8; j_++)                                      \
            BUF[j_] = __ldg((BASE) + ((K0) + j_) * UO + ub);                \
    } while (0)

// phase A block bodies
#define BODYA_WR(K0, BUF)                                                   \
    do {                                                                    \
        _Pragma("unroll")                                                   \
        for (int j_ = 0; j_ < 8; j_++) {                                    \
            int k_ = (K0) + j_;                                             \
            float4 w2_ = wbig4[k_ * UI + us];                               \
            float4 wr_ = wsmall4[k_ * UI + us];                             \
            const float4* hq_ = (const float4*)(h1 + k_ * HR);              \
            float4 h1a_ = hq_[0], h1b_ = hq_[1];                            \
            float4 h1sel_ = hiq ? h1b_ : h1a_;                              \
            float4 h2q_ = *(const float4*)(h2 + k_ * HR + rs);              \
            acc8(a1, BUF[j_], h1a_, h1b_);                                  \
            acc4(a2, w2_, h1sel_);                                          \
            acc4(a2, wr_, h2q_);                                            \
        }                                                                   \
    } while (0)

#define BODYA_NW(K0, BUF)                                                   \
    do {                                                                    \
        _Pragma("unroll")                                                   \
        for (int j_ = 0; j_ < 8; j_++) {                                    \
            int k_ = (K0) + j_;                                             \
            float4 w2_ = wbig4[k_ * UI + us];                               \
            const float4* hq_ = (const float4*)(h1 + k_ * HR);              \
            float4 h1a_ = hq_[0], h1b_ = hq_[1];                            \
            float4 h1sel_ = hiq ? h1b_ : h1a_;                              \
            acc8(a1, BUF[j_], h1a_, h1b_);                                  \
            acc4(a2, w2_, h1sel_);                                          \
        }                                                                   \
    } while (0)

// phase B block bodies
#define BODYB_WR(K0, BUF)                                                   \
    do {                                                                    \
        _Pragma("unroll")                                                   \
        for (int j_ = 0; j_ < 8; j_++) {                                    \
            int k_ = (K0) + j_;                                             \
            float4 wk_ = wbig4[k_ * UO + ub];                               \
            float4 w3_ = wsmall4[k_ * UI + us];                             \
            const float4* h4q_ = (const float4*)(h4 + k_ * HR);             \
            float4 h4a_ = h4q_[0], h4b_ = h4q_[1];                          \
            const float4* h3q_ = (const float4*)(h3 + k_ * HR);             \
            float4 h3a_ = h3q_[0], h3b_ = h3q_[1];                          \
            float4 h3sel_ = hiq ? h3b_ : h3a_;                              \
            acc8(a4, BUF[j_], h4a_, h4b_);                                  \
            acc8(a4, wk_, h3a_, h3b_);                                      \
            acc4(a3, w3_, h3sel_);                                          \
        }                                                                   \
    } while (0)

#define BODYB_NW(K0, BUF)                                                   \
    do {                                                                    \
        _Pragma("unroll")                                                   \
        for (int j_ = 0; j_ < 8; j_++) {                                    \
            const float4* h4q_ = (const float4*)(h4 + ((K0) + j_) * HR);    \
            acc8(a4, BUF[j_], h4q_[0], h4q_[1]);                            \
        }                                                                   \
    } while (0)

// ---------------- main: ping-pong pipelined LDG + smem weights ----------------
__global__ __launch_bounds__(NTHR, 1)
void lstm_ae_kernel(const float* __restrict__ x,
                    const float* __restrict__ b1,
                    float* __restrict__ out) {
    extern __shared__ __align__(16) float sm[];
    float* wbig   = sm + SM_WBIG;     // Wk2f (phase A) / Wk4f (phase B)
    float* wsmall = sm + SM_WSMALL;   // Wr2t (phase A) / Wr3t (phase B)
    float* wds    = sm + SM_WDS;
    float* bds    = sm + SM_BDS;

    const int tid  = threadIdx.x;
    const int half = tid >> 7;
    const int ltid = tid & 127;
    const int bid  = 1 + half;
    const int row0 = blockIdx.x * BT + half * HR;

    float* h1 = sm + SM_H1 + half * (UO * HR);
    float* h2 = sm + SM_H2 + half * (UI * HR);
    float* h3 = sm + SM_H3 + half * (UI * HR);
    float* h4 = sm + SM_H4 + half * (UO * HR);
    float* xh = sm + SM_XS + half * (FDIM * HR);

    const int ub = ltid;                 // big GEMMs: u-quad, all 8 rows
    const int us = ltid & 63;            // small GEMMs: u-quad
    const int rs = (ltid >> 6) * 4;      // small GEMMs: row-quad offset (0 or 4)
    const bool hiq = (ltid >= 64);       // warp-uniform: which quad rs selects

    // zero state, load dense weights, stage phase-A smem weights
    for (int i = tid; i < UO * HR * 2; i += NTHR) { sm[SM_H1 + i] = 0.f; sm[SM_H4 + i] = 0.f; }
    for (int i = tid; i < UI * HR * 2; i += NTHR) { sm[SM_H2 + i] = 0.f; sm[SM_H3 + i] = 0.f; }
    for (int i = tid; i < UO * FDIM; i += NTHR) wds[i] = g_Wdf[i];
    if (tid < FDIM) bds[tid] = g_bdf[tid];
    if (ltid < HR * FDIM) {
        int r = ltid >> 3, k = ltid & 7;
        xh[k * HR + r] = x[(size_t)(row0 + r) * TDIM * FDIM + k];
    }
    {
        float4* d1 = (float4*)wbig;
        const float4* s1 = (const float4*)g_Wk2f;
        for (int i = tid; i < N_WK2F / 4; i += NTHR) d1[i] = s1[i];
        float4* d2 = (float4*)wsmall;
        const float4* s2 = (const float4*)g_Wr2t;
        for (int i = tid; i < N_WR2T / 4; i += NTHR) d2[i] = s2[i];
    }

    float bb1[4], bb2[4], bb4[4];
#pragma unroll
    for (int g = 0; g < 4; g++) {
        bb1[g] = b1[g * UO + ub];
        bb2[g] = g_b2f[g * UI + us];
        bb4[g] = g_b4f[g * UO + ub];
    }

    float c1v[8], c4v[8], c2v[4], c3v[4];
#pragma unroll
    for (int i = 0; i < 8; i++) { c1v[i] = 0.f; c4v[i] = 0.f; }
#pragma unroll
    for (int i = 0; i < 4; i++) { c2v[i] = 0.f; c3v[i] = 0.f; }

    const float4* Wk1t = (const float4*)g_Wk1t;
    const float4* Wr1t = (const float4*)g_Wr1t;
    const float4* Wr4t = (const float4*)g_Wr4t;
    const float4* Wk3f = (const float4*)g_Wk3f;
    const float4* wbig4   = (const float4*)wbig;
    const float4* wsmall4 = (const float4*)wsmall;

    __syncthreads();

    // ========== Phase A: LSTM1(t) fused with LSTM2(t-1), pipelined ==========
    // Loop-top invariant: h1 = h1(t-1), h2 = h2(t-2), xh = x(t).
    for (int t = 0; t < TDIM; t++) {
        float2 a1[4][4];
        init_acc<4>(a1, bb1);
        float2 a2[4][2];
        init_acc<2>(a2, bb2);

        float4 wA[8], wB[8];

        // stage x weights + block-0 of Wr1t, then consume x (covers block-0 latency)
        {
            float4 xw[FDIM];
#pragma unroll
            for (int k = 0; k < FDIM; k++) xw[k] = __ldg(Wk1t + k * UO + ub);
            LD8(wA, Wr1t, 0);
#pragma unroll
            for (int k = 0; k < FDIM; k++) {
                const float4* xq = (const float4*)(xh + k * HR);
                acc8(a1, xw[k], xq[0], xq[1]);
            }
        }
        // region 1 (k<64, with Wr2): ping-pong, prefetch next block before consume
#pragma unroll 1
        for (int k0 = 0; k0 < 64; k0 += 16) {
            LD8(wB, Wr1t, k0 + 8);
            BODYA_WR(k0, wA);
            LD8(wA, Wr1t, k0 + 16);        // at k0=48 this preloads block 64
            BODYA_WR(k0 + 8, wB);
        }
        // region 2 (k 64..127): wA already holds block 64
#pragma unroll 1
        for (int k0 = 64; k0 < 128; k0 += 16) {
            LD8(wB, Wr1t, k0 + 8);
            BODYA_NW(k0, wA);
            LD8(wA, Wr1t, (k0 + 16) & 127);  // wrap keeps address valid
            BODYA_NW(k0 + 8, wB);
        }

        barsync(bid);  // old-state reads complete

        gates_write<4>(a1, c1v, h1 + ub * HR);                  // h1(t)
        if (t > 0) gates_write<2>(a2, c2v, h2 + us * HR + rs);  // h2(t-1)
        if (t + 1 < TDIM && ltid < HR * FDIM) {                 // x(t+1)
            int r = ltid >> 3, k = ltid & 7;
            xh[k * HR + r] = x[(size_t)(row0 + r) * TDIM * FDIM + (t + 1) * FDIM + k];
        }
        barsync(bid);  // new state visible
    }

    // epilogue A: h2(127) from h1(127), h2(126)
    {
        float2 a2[4][2];
        init_acc<2>(a2, bb2);
#pragma unroll 4
        for (int k = 0; k < UI; k++) {
            float4 w2 = wbig4[k * UI + us];
            float4 wr = wsmall4[k * UI + us];
            float4 h1sel = *(const float4*)(h1 + k * HR + rs);
            float4 h2q  = *(const float4*)(h2 + k * HR + rs);
            acc4(a2, w2, h1sel);
            acc4(a2, wr, h2q);
        }
#pragma unroll 4
        for (int k = UI; k < UO; k++) {
            float4 w2 = wbig4[k * UI + us];
            float4 h1sel = *(const float4*)(h1 + k * HR + rs);
            acc4(a2, w2, h1sel);
        }
        barsync(bid);
        gates_write<2>(a2, c2v, h2 + us * HR + rs);  // h2(127)
    }

    // ===== transition: xz3 = enc_bn @ Wk3f + b3f; reload smem for phase B ====
    __syncthreads();   // join halves; h2 final everywhere
    float2 x3[4][2];
    {
        float bb3[4];
#pragma unroll
        for (int g = 0; g < 4; g++) bb3[g] = g_b3f[g * UI + us];
        init_acc<2>(x3, bb3);
#pragma unroll 4
        for (int k = 0; k < UI; k++) {
            float4 w = __ldg(Wk3f + k * UI + us);
            float4 hq = *(const float4*)(h2 + k * HR + rs);
            acc4(x3, w, hq);
        }
    }
    {
        float4* d1 = (float4*)wbig;
        const float4* s1 = (const float4*)g_Wk4f;
        for (int i = tid; i < N_WK4F / 4; i += NTHR) d1[i] = s1[i];
        float4* d2 = (float4*)wsmall;
        const float4* s2 = (const float4*)g_Wr3t;
        for (int i = tid; i < N_WR3T / 4; i += NTHR) d2[i] = s2[i];
    }
    __syncthreads();   // phase-B weights staged

    // ========== Phase B: LSTM3(t) fused with LSTM4(t-1) + Dense(t-2) ========
    // Loop-top invariant: h3 = h3(t-1), h4 = h4(t-2).
    const int dr = ltid >> 3, dc = ltid & 7;
    for (int t = 0; t < TDIM; t++) {
        float2 a3[4][2];
#pragma unroll
        for (int g = 0; g < 4; g++) { a3[g][0] = x3[g][0]; a3[g][1] = x3[g][1]; }
        float2 a4[4][4];
        init_acc<4>(a4, bb4);

        float4 wA[8], wB[8];
        LD8(wA, Wr4t, 0);

        // dense head out(t-2) from h4(t-2) — covers block-0 latency
        if (t >= 2 && ltid < HR * FDIM) {
            float acc = bds[dc];
#pragma unroll 8
            for (int k = 0; k < UO; k++) acc += h4[k * HR + dr] * wds[k * FDIM + dc];
            out[(size_t)(row0 + dr) * TDIM * FDIM + (t - 2) * FDIM + dc] = acc;
        }

        // region 1 (k<64, with Wk4f + Wr3): ping-pong
#pragma unroll 1
        for (int k0 = 0; k0 < 64; k0 += 16) {
            LD8(wB, Wr4t, k0 + 8);
            BODYB_WR(k0, wA);
            LD8(wA, Wr4t, k0 + 16);        // at k0=48 preloads block 64
            BODYB_WR(k0 + 8, wB);
        }
        // region 2 (k 64..127): Wr4·h4 only
#pragma unroll 1
        for (int k0 = 64; k0 < 128; k0 += 16) {
            LD8(wB, Wr4t, k0 + 8);
            BODYB_NW(k0, wA);
            LD8(wA, Wr4t, (k0 + 16) & 127);
            BODYB_NW(k0 + 8, wB);
        }

        barsync(bid);  // old-state reads complete

        gates_write<2>(a3, c3v, h3 + us * HR + rs);             // h3(t)
        if (t > 0) gates_write<4>(a4, c4v, h4 + ub * HR);       // h4(t-1)
        barsync(bid);  // new state visible
    }

    // epilogue B: h4(127) from h4(126), h3(127); dense out(126), out(127)
    {
        float2 a4[4][4];
        init_acc<4>(a4, bb4);
#pragma unroll 4
        for (int k = 0; k < UI; k++) {
            float4 w4 = __ldg(Wr4t + k * UO + ub);
            float4 wk = wbig4[k * UO + ub];
            const float4* h4q = (const float4*)(h4 + k * HR);
            const float4* h3q = (const float4*)(h3 + k * HR);
            acc8(a4, w4, h4q[0], h4q[1]);
            acc8(a4, wk, h3q[0], h3q[1]);
        }
#pragma unroll 4
        for (int k = UI; k < UO; k++) {
            float4 w4 = __ldg(Wr4t + k * UO + ub);
            const float4* h4q = (const float4*)(h4 + k * HR);
            acc8(a4, w4, h4q[0], h4q[1]);
        }
        if (ltid < HR * FDIM) {  // out(126) from h4(126)
            float acc = bds[dc];
#pragma unroll 8
            for (int k = 0; k < UO; k++) acc += h4[k * HR + dr] * wds[k * FDIM + dc];
            out[(size_t)(row0 + dr) * TDIM * FDIM + 126 * FDIM + dc] = acc;
        }
        barsync(bid);
        gates_write<4>(a4, c4v, h4 + ub * HR);  // h4(127)
        barsync(bid);
        if (ltid < HR * FDIM) {  // out(127)
            float acc = bds[dc];
#pragma unroll 8
            for (int k = 0; k < UO; k++) acc += h4[k * HR + dr] * wds[k * FDIM + dc];
            out[(size_t)(row0 + dr) * TDIM * FDIM + 127 * FDIM + dc] = acc;
        }
    }
}

// ---------------- launch ------------------------------------------------------
extern "C" void kernel_launch(void* const* d_in, const int* in_sizes, int n_in,
                              void* d_out, int out_size) {
    const float* x   = (const float*)d_in[0];
    const float* Wk1 = (const float*)d_in[1];
    const float* Wr1 = (const float*)d_in[2];
    const float* b1  = (const float*)d_in[3];
    const float* g1  = (const float*)d_in[4];
    const float* be1 = (const float*)d_in[5];
    const float* m1  = (const float*)d_in[6];
    const float* v1  = (const float*)d_in[7];
    const float* Wk2 = (const float*)d_in[8];
    const float* Wr2 = (const float*)d_in[9];
    const float* b2  = (const float*)d_in[10];
    const float* g2  = (const float*)d_in[11];
    const float* be2 = (const float*)d_in[12];
    const float* m2  = (const float*)d_in[13];
    const float* v2  = (const float*)d_in[14];
    const float* Wk3 = (const float*)d_in[15];
    const float* Wr3 = (const float*)d_in[16];
    const float* b3  = (const float*)d_in[17];
    const float* g3  = (const float*)d_in[18];
    const float* be3 = (const float*)d_in[19];
    const float* m3  = (const float*)d_in[20];
    const float* v3  = (const float*)d_in[21];
    const float* Wk4 = (const float*)d_in[22];
    const float* Wr4 = (const float*)d_in[23];
    const float* b4  = (const float*)d_in[24];
    const float* g4  = (const float*)d_in[25];
    const float* be4 = (const float*)d_in[26];
    const float* m4  = (const float*)d_in[27];
    const float* v4  = (const float*)d_in[28];
    const float* Wd  = (const float*)d_in[29];
    const float* bd  = (const float*)d_in[30];

    static bool attr_set = false;
    if (!attr_set) {
        cudaFuncSetAttribute(lstm_ae_kernel,
                             cudaFuncAttributeMaxDynamicSharedMemorySize, SMEM_BYTES);
        attr_set = true;
    }

    prep_all<<<(NTOT + 255) / 256, 256>>>(Wk1, Wr1, Wr2, Wr3, Wr4,
                                          Wk2, b2, Wk3, b3, Wk4, b4, Wd, bd,
                                          g1, be1, m1, v1, g2, be2, m2, v2,
                                          g3, be3, m3, v3, g4, be4, m4, v4);
    lstm_ae_kernel<<<BDIM / BT, NTHR, SMEM_BYTES>>>(x, b1, (float*)d_out);
}